// round 8
// baseline (speedup 1.0000x reference)
#include <cuda_runtime.h>
#include <cuda_bf16.h>
#include <math.h>
#include <cstdint>

#define BB 8
#define CH 128
#define CC 256
#define HW 4096
#define PP 32768      // BB*HW
#define KBIG 1152     // 128 ic * 9 taps

// ---------------- scratch (static device globals; no runtime alloc) --------
static __device__ float  g_h1 [BB*CC*HW];     // fused upcat+depthwise1 out
static __device__ float  g_h  [BB*CH*HW];     // pointwise out
static __device__ float  g_offb[BB*18*HW];    // offsets
static __device__ float  g_mb [BB*9*HW];      // modulation (sigmoid)
static __device__ float  g_d  [BB*CH*HW];     // deform conv out
static __device__ float  g_u  [BB*CH*HW];     // depthwise2 out
static __device__ float  g_s1 [2*CH];         // bn1 mean / rstd
static __device__ float  g_s2 [2*CH];         // bn2 mean / rstd
static __device__ float  g_p1s[CH*256];       // dgemm per-CTA channel sums
static __device__ float  g_p1q[CH*256];       // dgemm per-CTA channel sumsq
static __device__ float  g_p2s[BB*CH];        // dw2 per-CTA sums
static __device__ float  g_p2q[BB*CH];        // dw2 per-CTA sumsq
static __device__ __nv_bfloat16 g_wA [18*16384];  // dcn w: hi+lo SW128 images
static __device__ __nv_bfloat16 g_pwA[4*16384];   // pw w: hi+lo SW128 images
static __device__ __nv_bfloat16 g_omA[18*4096];   // off+mask w: hi+lo images

#define SW128(o)   ((o) ^ (((o) >> 3) & 0x70))

__device__ __forceinline__ uint32_t smem_u32(const void* p) {
    uint32_t a;
    asm("{ .reg .u64 t; cvta.to.shared.u64 t, %1; cvt.u32.u64 %0, t; }"
        : "=r"(a) : "l"(p));
    return a;
}
__device__ __forceinline__ void ldmx4(uint32_t* r, uint32_t addr) {
    asm volatile("ldmatrix.sync.aligned.m8n8.x4.shared.b16 {%0,%1,%2,%3}, [%4];"
                 : "=r"(r[0]), "=r"(r[1]), "=r"(r[2]), "=r"(r[3]) : "r"(addr));
}
__device__ __forceinline__ void mma_bf16(float* d, const uint32_t* a,
                                         uint32_t b0, uint32_t b1) {
    asm volatile("mma.sync.aligned.m16n8k16.row.col.f32.bf16.bf16.f32 "
                 "{%0,%1,%2,%3}, {%4,%5,%6,%7}, {%8,%9}, {%0,%1,%2,%3};"
                 : "+f"(d[0]), "+f"(d[1]), "+f"(d[2]), "+f"(d[3])
                 : "r"(a[0]), "r"(a[1]), "r"(a[2]), "r"(a[3]), "r"(b0), "r"(b1));
}
__device__ __forceinline__ void split_store(unsigned char* hi, unsigned char* lo,
                                            uint32_t off, float v0, float v1) {
    __nv_bfloat16 h0 = __float2bfloat16(v0);
    __nv_bfloat16 h1 = __float2bfloat16(v1);
    __nv_bfloat16 l0 = __float2bfloat16(v0 - __bfloat162float(h0));
    __nv_bfloat16 l1 = __float2bfloat16(v1 - __bfloat162float(h1));
    *(uint32_t*)(hi + off) = ((uint32_t)__bfloat16_as_ushort(h1) << 16) | __bfloat16_as_ushort(h0);
    *(uint32_t*)(lo + off) = ((uint32_t)__bfloat16_as_ushort(l1) << 16) | __bfloat16_as_ushort(l0);
}
__device__ __forceinline__ void hi_store(unsigned char* hi, uint32_t off,
                                         float v0, float v1) {
    __nv_bfloat16 h0 = __float2bfloat16(v0);
    __nv_bfloat16 h1 = __float2bfloat16(v1);
    *(uint32_t*)(hi + off) = ((uint32_t)__bfloat16_as_ushort(h1) << 16) | __bfloat16_as_ushort(h0);
}

// ---------------- K0: weight prep (hi/lo split + SW128 images) --------------
__global__ __launch_bounds__(256) void k_prep(const float* __restrict__ dcn_w,
                                              const float* __restrict__ pw_w,
                                              const float* __restrict__ p_w,
                                              const float* __restrict__ m_w) {
    int i = blockIdx.x * 256 + threadIdx.x;
    if (i < 18*16384) {
        int c = i >> 14, r = i & 16383;
        int s = r >> 13, e = r & 8191;
        int oc = e >> 6, ic = e & 63;
        int tap = c >> 1, ichalf = c & 1;
        float val = dcn_w[oc*KBIG + (ichalf*64 + ic)*9 + tap];
        __nv_bfloat16 hi = __float2bfloat16(val);
        __nv_bfloat16 out = s ? __float2bfloat16(val - __bfloat162float(hi)) : hi;
        g_wA[(size_t)c*16384 + s*8192 + (SW128((uint32_t)(oc*128 + ic*2)) >> 1)] = out;
        return;
    }
    i -= 18*16384;
    if (i < 4*16384) {
        int c = i >> 14, r = i & 16383;
        int s = r >> 13, e = r & 8191;
        int oc = e >> 6, ic = e & 63;
        float val = pw_w[oc*CC + c*64 + ic];
        __nv_bfloat16 hi = __float2bfloat16(val);
        __nv_bfloat16 out = s ? __float2bfloat16(val - __bfloat162float(hi)) : hi;
        g_pwA[(size_t)c*16384 + s*8192 + (SW128((uint32_t)(oc*128 + ic*2)) >> 1)] = out;
        return;
    }
    i -= 4*16384;
    if (i < 18*4096) {
        int c = i >> 12, r = i & 4095;
        int s = r >> 11, e = r & 2047;
        int oc = e >> 6, ic = e & 63;
        int tap = c >> 1, ichalf = c & 1;
        int icg = ichalf*64 + ic;
        float val = 0.f;
        if (oc < 18)      val = p_w[oc*KBIG + icg*9 + tap];
        else if (oc < 27) val = m_w[(oc-18)*KBIG + icg*9 + tap];
        __nv_bfloat16 hi = __float2bfloat16(val);
        __nv_bfloat16 out = s ? __float2bfloat16(val - __bfloat162float(hi)) : hi;
        g_omA[(size_t)c*4096 + s*2048 + (SW128((uint32_t)(oc*128 + ic*2)) >> 1)] = out;
    }
}

// ---------------- K1: fused bilinear-up2x + concat + depthwise1 -------------
__global__ __launch_bounds__(256) void k_updw1(const float* __restrict__ x1,
                                               const float* __restrict__ x2,
                                               const float* __restrict__ w,
                                               const float* __restrict__ bias) {
    __shared__ float T[66*68];
    __shared__ float X1[32*33];
    int tid = threadIdx.x;
    int blk = blockIdx.x;
    int b = blk >> 8, ch = blk & 255;

    if (ch < CH) {
        const float* img = x2 + (size_t)(b*CH + ch)*HW;
        for (int e = tid; e < 66*66; e += 256) {
            int r = e/66, c = e - (e/66)*66;
            int rr = r - 1, cc = c - 1;
            T[r*68 + c] = ((unsigned)rr < 64u && (unsigned)cc < 64u) ? img[rr*64 + cc] : 0.f;
        }
    } else {
        const float* img = x1 + ((size_t)(b*CH + ch - CH))*1024;
        for (int e = tid; e < 1024; e += 256)
            X1[(e >> 5)*33 + (e & 31)] = img[e];
        __syncthreads();
        for (int e = tid; e < 66*66; e += 256) {
            int r = e/66, c = e - (e/66)*66;
            int rr = r - 1, cc = c - 1;
            float v = 0.f;
            if ((unsigned)rr < 64u && (unsigned)cc < 64u) {
                float sr = (float)rr * (31.0f/63.0f);
                float sc = (float)cc * (31.0f/63.0f);
                int i0 = min((int)sr, 30);
                int j0 = min((int)sc, 30);
                float ty = sr - (float)i0;
                float tx = sc - (float)j0;
                float a00 = X1[i0*33 + j0],     a10 = X1[(i0+1)*33 + j0];
                float a01 = X1[i0*33 + j0 + 1], a11 = X1[(i0+1)*33 + j0 + 1];
                v = (a00*(1.f-ty) + a10*ty)*(1.f-tx) + (a01*(1.f-ty) + a11*ty)*tx;
            }
            T[r*68 + c] = v;
        }
    }
    __syncthreads();

    const float* wc = w + ch*9;
    float w0 = wc[0], w1 = wc[1], w2 = wc[2], w3 = wc[3], w4 = wc[4],
          w5 = wc[5], w6 = wc[6], w7 = wc[7], w8 = wc[8];
    float bb = bias[ch];
    float* dst = g_h1 + (size_t)blk*HW;
#pragma unroll
    for (int i = 0; i < 16; i++) {
        int px = i*256 + tid;
        int r = px >> 6, c = px & 63;
        const float* t0 = T + r*68 + c;
        dst[px] = bb
            + w0*t0[0]     + w1*t0[1]     + w2*t0[2]
            + w3*t0[68]    + w4*t0[69]    + w5*t0[70]
            + w6*t0[136]   + w7*t0[137]   + w8*t0[138];
    }
}

// ---------------- K3: pointwise 256->128 via mma.sync bf16x3 ----------------
#define SMEM_PW (2*65536)
__device__ __forceinline__ void pw_build(unsigned char* nb, int b, int c,
                                         int hw0, int tid) {
    float4* dstA = (float4*)nb;
    const float4* srcA = (const float4*)((const unsigned char*)g_pwA + (size_t)c*32768);
#pragma unroll
    for (int i = 0; i < 8; i++) dstA[tid + i*256] = srcA[tid + i*256];
    int px4 = (tid & 31) * 4;
    int icb = (tid >> 5) * 8;
    const float* base = g_h1 + ((size_t)(b*CC + c*64 + icb))*HW + hw0 + px4;
    unsigned char* bhi = nb + 32768;
    unsigned char* blo = bhi + 16384;
#pragma unroll
    for (int jc = 0; jc < 8; jc += 2) {
        float4 a = *(const float4*)(base);
        float4 d = *(const float4*)(base + HW);
        base += 2*HW;
        int k2 = (icb + jc) * 2;
        split_store(bhi, blo, SW128((uint32_t)((px4+0)*128 + k2)), a.x, d.x);
        split_store(bhi, blo, SW128((uint32_t)((px4+1)*128 + k2)), a.y, d.y);
        split_store(bhi, blo, SW128((uint32_t)((px4+2)*128 + k2)), a.z, d.z);
        split_store(bhi, blo, SW128((uint32_t)((px4+3)*128 + k2)), a.w, d.w);
    }
}

__global__ __launch_bounds__(256, 1) void k_pw_tc(const float* __restrict__ bias) {
    extern __shared__ __align__(1024) unsigned char smem[];
    uint32_t sb = smem_u32(smem);
    int tid  = threadIdx.x;
    int lane = tid & 31;
    int wid  = tid >> 5;
    int pxg0 = blockIdx.x * 128;
    int b   = pxg0 >> 12;
    int hw0 = pxg0 & 4095;

    int ocb  = (wid >> 2) * 64;
    int pxb  = (wid & 3) * 32;
    int lrow = lane & 15;
    int lkh  = (lane >> 4) * 16;

    pw_build(smem, b, 0, hw0, tid);
    __syncthreads();

    float acc[4][4][4];
#pragma unroll
    for (int mt = 0; mt < 4; mt++)
#pragma unroll
        for (int nt = 0; nt < 4; nt++)
#pragma unroll
            for (int q = 0; q < 4; q++) acc[mt][nt][q] = 0.f;

    for (int c = 0; c < 4; c++) {
        int p = c & 1;
        uint32_t tb = sb + p*65536;
#pragma unroll
        for (int ks = 0; ks < 4; ks++) {
            int kb = ks*32 + lkh;
            uint32_t ah[4][4], al[4][4], bb[2][4];
#pragma unroll
            for (int mt = 0; mt < 4; mt++)
                ldmx4(ah[mt], tb + SW128((uint32_t)((ocb + mt*16 + lrow)*128 + kb)));
#pragma unroll
            for (int ntp = 0; ntp < 2; ntp++)
                ldmx4(bb[ntp], tb + 32768 + SW128((uint32_t)((pxb + ntp*16 + lrow)*128 + kb)));
#pragma unroll
            for (int mt = 0; mt < 4; mt++)
#pragma unroll
                for (int nt = 0; nt < 4; nt++)
                    mma_bf16(acc[mt][nt], ah[mt], bb[nt>>1][nt&1], bb[nt>>1][(nt&1)+2]);
#pragma unroll
            for (int mt = 0; mt < 4; mt++)
                ldmx4(al[mt], tb + 16384 + SW128((uint32_t)((ocb + mt*16 + lrow)*128 + kb)));
#pragma unroll
            for (int mt = 0; mt < 4; mt++)
#pragma unroll
                for (int nt = 0; nt < 4; nt++)
                    mma_bf16(acc[mt][nt], al[mt], bb[nt>>1][nt&1], bb[nt>>1][(nt&1)+2]);
#pragma unroll
            for (int ntp = 0; ntp < 2; ntp++)
                ldmx4(bb[ntp], tb + 49152 + SW128((uint32_t)((pxb + ntp*16 + lrow)*128 + kb)));
#pragma unroll
            for (int mt = 0; mt < 4; mt++)
#pragma unroll
                for (int nt = 0; nt < 4; nt++)
                    mma_bf16(acc[mt][nt], ah[mt], bb[nt>>1][nt&1], bb[nt>>1][(nt&1)+2]);
        }
        if (c < 3) pw_build(smem + (1-p)*65536, b, c + 1, hw0, tid);
        __syncthreads();
    }

    int g  = lane >> 2;
    int cx = (lane & 3) * 2;
#pragma unroll
    for (int mt = 0; mt < 4; mt++) {
#pragma unroll
        for (int nt = 0; nt < 4; nt++) {
            int oc = ocb + mt*16 + g;
            int px = pxb + nt*8 + cx;
            float b0 = bias[oc], b1 = bias[oc + 8];
            float* d0 = g_h + ((size_t)(b*CH + oc))*HW + hw0 + px;
            float* d1 = g_h + ((size_t)(b*CH + oc + 8))*HW + hw0 + px;
            *(float2*)d0 = make_float2(acc[mt][nt][0] + b0, acc[mt][nt][1] + b0);
            *(float2*)d1 = make_float2(acc[mt][nt][2] + b1, acc[mt][nt][3] + b1);
        }
    }
}

// ---------------- K4: offset+mask conv via mma.sync (A hi+lo, B hi only) ----
#define SM_NOFF  0
#define SM_OMT   5120
#define OM_BUF   24576   // Ahi 4096 | Alo 4096 | Bhi 16384
#define SMEM_OM  (SM_OMT + 2*OM_BUF)
__global__ __launch_bounds__(256, 3) void k_offmask_tc(const float* __restrict__ pb,
                                                       const float* __restrict__ mb) {
    extern __shared__ __align__(1024) unsigned char smem[];
    uint32_t sb = smem_u32(smem);
    int* noff = (int*)(smem + SM_NOFF);
    int tid  = threadIdx.x;
    int lane = tid & 31;
    int wid  = tid >> 5;
    int pxg0 = blockIdx.x * 128;
    int b   = pxg0 >> 12;
    int hw0 = pxg0 & 4095;

    int pxB  = tid & 127;
    int half = tid >> 7;
    int pxw  = wid * 16;
    int lrow = lane & 15;
    int lkh  = (lane >> 4) * 16;

    for (int e = tid; e < 1152; e += 256) {
        int t = e >> 7, h = e & 127;
        int hw = hw0 + h;
        int r = hw >> 6, c = hw & 63;
        int dy = t/3 - 1, dx = t%3 - 1;
        int rr = r + dy, cc = c + dx;
        noff[e] = ((unsigned)rr < 64u && (unsigned)cc < 64u) ? (rr*64 + cc) : -1;
    }
    __syncthreads();

    {
        unsigned char* nb = smem + SM_OMT;
        float4* dstA = (float4*)nb;
        const float4* srcA = (const float4*)((const unsigned char*)g_omA);
#pragma unroll
        for (int i = 0; i < 2; i++) dstA[tid + i*256] = srcA[tid + i*256];
        int idx = noff[pxB];
        const float* img = g_h + ((size_t)(b*CH + half*32))*HW;
        unsigned char* bhi = nb + 8192;
#pragma unroll
        for (int ip = 0; ip < 16; ip++) {
            float v0 = (idx >= 0) ? img[idx] : 0.f; img += HW;
            float v1 = (idx >= 0) ? img[idx] : 0.f; img += HW;
            hi_store(bhi, SW128((uint32_t)(pxB*128 + (half*32 + ip*2)*2)), v0, v1);
        }
    }
    __syncthreads();

    float acc[2][2][4];
#pragma unroll
    for (int mt = 0; mt < 2; mt++)
#pragma unroll
        for (int nt = 0; nt < 2; nt++)
#pragma unroll
            for (int q = 0; q < 4; q++) acc[mt][nt][q] = 0.f;

    for (int c = 0; c < 18; c++) {
        int p = c & 1;
        uint32_t tb = sb + SM_OMT + p*OM_BUF;
#pragma unroll
        for (int ks = 0; ks < 4; ks++) {
            int kb = ks*32 + lkh;
            uint32_t ah[2][4], al[2][4], bh[4];
#pragma unroll
            for (int mt = 0; mt < 2; mt++)
                ldmx4(ah[mt], tb + SW128((uint32_t)((mt*16 + lrow)*128 + kb)));
            ldmx4(bh, tb + 8192 + SW128((uint32_t)((pxw + lrow)*128 + kb)));
#pragma unroll
            for (int mt = 0; mt < 2; mt++)
#pragma unroll
                for (int nt = 0; nt < 2; nt++)
                    mma_bf16(acc[mt][nt], ah[mt], bh[nt], bh[nt+2]);
#pragma unroll
            for (int mt = 0; mt < 2; mt++)
                ldmx4(al[mt], tb + 4096 + SW128((uint32_t)((mt*16 + lrow)*128 + kb)));
#pragma unroll
            for (int mt = 0; mt < 2; mt++)
#pragma unroll
                for (int nt = 0; nt < 2; nt++)
                    mma_bf16(acc[mt][nt], al[mt], bh[nt], bh[nt+2]);
        }
        if (c < 17) {
            int cn = c + 1;
            unsigned char* nb = smem + SM_OMT + (1-p)*OM_BUF;
            float4* dstA = (float4*)nb;
            const float4* srcA = (const float4*)((const unsigned char*)g_omA + (size_t)cn*8192);
#pragma unroll
            for (int i = 0; i < 2; i++) dstA[tid + i*256] = srcA[tid + i*256];
            int tap = cn >> 1, ichalf = cn & 1;
            int idx = noff[tap*128 + pxB];
            const float* img = g_h + ((size_t)(b*CH + ichalf*64 + half*32))*HW;
            unsigned char* bhi = nb + 8192;
#pragma unroll
            for (int ip = 0; ip < 16; ip++) {
                float v0 = (idx >= 0) ? img[idx] : 0.f; img += HW;
                float v1 = (idx >= 0) ? img[idx] : 0.f; img += HW;
                hi_store(bhi, SW128((uint32_t)(pxB*128 + (half*32 + ip*2)*2)), v0, v1);
            }
        }
        __syncthreads();
    }

    int g  = lane >> 2;
    int cx = (lane & 3) * 2;
#pragma unroll
    for (int mt = 0; mt < 2; mt++) {
#pragma unroll
        for (int nt = 0; nt < 2; nt++) {
            int px = hw0 + pxw + nt*8 + cx;
#pragma unroll
            for (int h2 = 0; h2 < 2; h2++) {
                int oc = mt*16 + g + h2*8;
                float v0 = acc[mt][nt][h2*2], v1 = acc[mt][nt][h2*2 + 1];
                if (oc < 18) {
                    float bbv = pb[oc];
                    float* d = g_offb + (size_t)(b*18 + oc)*HW + px;
                    *(float2*)d = make_float2(v0 + bbv, v1 + bbv);
                } else if (oc < 27) {
                    float bbv = mb[oc - 18];
                    float* d = g_mb + (size_t)(b*9 + oc - 18)*HW + px;
                    *(float2*)d = make_float2(1.f/(1.f + expf(-(v0 + bbv))),
                                              1.f/(1.f + expf(-(v1 + bbv))));
                }
            }
        }
    }
}

// ---------------- K5: deform conv via mma.sync bf16x3 + stats epilogue ------
#define SM_SI    0
#define SM_SW    18432
#define SM_TILE  36864
#define SMEM_DG  (SM_TILE + 2*65536)

__device__ __forceinline__ float dsample(const float* img, int4 id, float4 w) {
    float v = 0.f;
    if (id.x >= 0) v += w.x * img[id.x];
    if (id.y >= 0) v += w.y * img[id.y];
    if (id.z >= 0) v += w.z * img[id.z];
    if (id.w >= 0) v += w.w * img[id.w];
    return v;
}

__global__ __launch_bounds__(256, 1) void k_dgemm_tc() {
    extern __shared__ __align__(1024) unsigned char smem[];
    uint32_t sb = smem_u32(smem);
    int tid  = threadIdx.x;
    int lane = tid & 31;
    int wid  = tid >> 5;
    int pxg0 = blockIdx.x * 128;
    int b   = pxg0 >> 12;
    int hw0 = pxg0 & 4095;

    int4*   si = (int4*)(smem + SM_SI);
    float4* sw = (float4*)(smem + SM_SW);

    for (int e = tid; e < 1152; e += 256) {
        int n = e >> 7, h = e & 127;
        int hw = hw0 + h;
        int r = hw >> 6, c = hw & 63;
        float ox = g_offb[(size_t)(b*18 + n)*HW + hw];
        float oy = g_offb[(size_t)(b*18 + 9 + n)*HW + hw];
        float px = (float)(r + 1) + (float)(n/3 - 1) + ox;
        float py = (float)(c + 1) + (float)(n%3 - 1) + oy;
        float fx = floorf(px), fy = floorf(py);
        float qx0 = fminf(fmaxf(fx,       0.f), 65.f);
        float qx1 = fminf(fmaxf(fx + 1.f, 0.f), 65.f);
        float qy0 = fminf(fmaxf(fy,       0.f), 65.f);
        float qy1 = fminf(fmaxf(fy + 1.f, 0.f), 65.f);
        float pxc = fminf(fmaxf(px, 0.f), 65.f);
        float pyc = fminf(fmaxf(py, 0.f), 65.f);
        float glt = (1.f + (qx0 - pxc)) * (1.f + (qy0 - pyc));
        float grb = (1.f - (qx1 - pxc)) * (1.f - (qy1 - pyc));
        float glb = (1.f + (qx0 - pxc)) * (1.f - (qy1 - pyc));
        float grt = (1.f - (qx1 - pxc)) * (1.f + (qy0 - pyc));
        float mod = g_mb[(size_t)(b*9 + n)*HW + hw];
        int ix0 = (int)qx0, ix1 = (int)qx1, iy0 = (int)qy0, iy1 = (int)qy1;
#define ENC(qx,qy) (((qx)>=1 && (qx)<=64 && (qy)>=1 && (qy)<=64) ? (((qx)-1)*64 + ((qy)-1)) : -1)
        si[e] = make_int4(ENC(ix0,iy0), ENC(ix1,iy1), ENC(ix0,iy1), ENC(ix1,iy0));
#undef ENC
        sw[e] = make_float4(glt*mod, grb*mod, glb*mod, grt*mod);
    }
    __syncthreads();

    int pxB  = tid & 127;
    int half = tid >> 7;
    int ocb  = (wid >> 2) * 64;
    int pxb  = (wid & 3) * 32;
    int lrow = lane & 15;
    int lkh  = (lane >> 4) * 16;

    {
        float4* dstA = (float4*)(smem + SM_TILE);
        const float4* srcA = (const float4*)((const unsigned char*)g_wA);
#pragma unroll
        for (int i = 0; i < 8; i++) dstA[tid + i*256] = srcA[tid + i*256];
        int4   id = si[pxB];
        float4 wc = sw[pxB];
        const float* img = g_h + ((size_t)(b*CH + half*32))*HW;
        unsigned char* bhi = smem + SM_TILE + 32768;
        unsigned char* blo = bhi + 16384;
#pragma unroll
        for (int ip = 0; ip < 16; ip++) {
            float v0 = dsample(img, id, wc); img += HW;
            float v1 = dsample(img, id, wc); img += HW;
            split_store(bhi, blo, SW128((uint32_t)(pxB*128 + (half*32 + ip*2)*2)), v0, v1);
        }
    }
    __syncthreads();

    float acc[4][4][4];
#pragma unroll
    for (int mt = 0; mt < 4; mt++)
#pragma unroll
        for (int nt = 0; nt < 4; nt++)
#pragma unroll
            for (int q = 0; q < 4; q++) acc[mt][nt][q] = 0.f;

    for (int c = 0; c < 18; c++) {
        int p = c & 1;
        uint32_t tb = sb + SM_TILE + p*65536;
#pragma unroll
        for (int ks = 0; ks < 4; ks++) {
            int kb = ks*32 + lkh;
            uint32_t ah[4][4], al[4][4], bb[2][4];
#pragma unroll
            for (int mt = 0; mt < 4; mt++)
                ldmx4(ah[mt], tb + SW128((uint32_t)((ocb + mt*16 + lrow)*128 + kb)));
#pragma unroll
            for (int ntp = 0; ntp < 2; ntp++)
                ldmx4(bb[ntp], tb + 32768 + SW128((uint32_t)((pxb + ntp*16 + lrow)*128 + kb)));
#pragma unroll
            for (int mt = 0; mt < 4; mt++)
#pragma unroll
                for (int nt = 0; nt < 4; nt++)
                    mma_bf16(acc[mt][nt], ah[mt], bb[nt>>1][nt&1], bb[nt>>1][(nt&1)+2]);
#pragma unroll
            for (int mt = 0; mt < 4; mt++)
                ldmx4(al[mt], tb + 16384 + SW128((uint32_t)((ocb + mt*16 + lrow)*128 + kb)));
#pragma unroll
            for (int mt = 0; mt < 4; mt++)
#pragma unroll
                for (int nt = 0; nt < 4; nt++)
                    mma_bf16(acc[mt][nt], al[mt], bb[nt>>1][nt&1], bb[nt>>1][(nt&1)+2]);
#pragma unroll
            for (int ntp = 0; ntp < 2; ntp++)
                ldmx4(bb[ntp], tb + 49152 + SW128((uint32_t)((pxb + ntp*16 + lrow)*128 + kb)));
#pragma unroll
            for (int mt = 0; mt < 4; mt++)
#pragma unroll
                for (int nt = 0; nt < 4; nt++)
                    mma_bf16(acc[mt][nt], ah[mt], bb[nt>>1][nt&1], bb[nt>>1][(nt&1)+2]);
        }
        if (c < 17) {
            int cn = c + 1;
            unsigned char* nb = smem + SM_TILE + (1-p)*65536;
            float4* dstA = (float4*)nb;
            const float4* srcA = (const float4*)((const unsigned char*)g_wA + (size_t)cn*32768);
#pragma unroll
            for (int i = 0; i < 8; i++) dstA[tid + i*256] = srcA[tid + i*256];
            int tap = cn >> 1, ichalf = cn & 1;
            int m = tap*128 + pxB;
            int4   id = si[m];
            float4 wc = sw[m];
            const float* img = g_h + ((size_t)(b*CH + ichalf*64 + half*32))*HW;
            unsigned char* bhi = nb + 32768;
            unsigned char* blo = bhi + 16384;
#pragma unroll
            for (int ip = 0; ip < 16; ip++) {
                float v0 = dsample(img, id, wc); img += HW;
                float v1 = dsample(img, id, wc); img += HW;
                split_store(bhi, blo, SW128((uint32_t)(pxB*128 + (half*32 + ip*2)*2)), v0, v1);
            }
        }
        __syncthreads();
    }

    int g  = lane >> 2;
    int cx = (lane & 3) * 2;
#pragma unroll
    for (int mt = 0; mt < 4; mt++) {
#pragma unroll
        for (int nt = 0; nt < 4; nt++) {
            int oc = ocb + mt*16 + g;
            int px = pxb + nt*8 + cx;
            float* d0 = g_d + ((size_t)(b*CH + oc))*HW + hw0 + px;
            float* d1 = g_d + ((size_t)(b*CH + oc + 8))*HW + hw0 + px;
            *(float2*)d0 = make_float2(acc[mt][nt][0], acc[mt][nt][1]);
            *(float2*)d1 = make_float2(acc[mt][nt][2], acc[mt][nt][3]);
        }
    }

    // ---- BN1 stats epilogue: per-CTA per-channel (sum, sumsq) ----
    float* sp = (float*)smem;          // [128][4]
    float* sq = sp + 512;              // [128][4]
#pragma unroll
    for (int mt = 0; mt < 4; mt++) {
#pragma unroll
        for (int h2 = 0; h2 < 2; h2++) {
            float s = 0.f, q = 0.f;
#pragma unroll
            for (int nt = 0; nt < 4; nt++) {
                float v0 = acc[mt][nt][h2*2], v1 = acc[mt][nt][h2*2 + 1];
                s += v0 + v1;
                q += v0*v0 + v1*v1;
            }
            s += __shfl_xor_sync(0xffffffffu, s, 1);
            q += __shfl_xor_sync(0xffffffffu, q, 1);
            s += __shfl_xor_sync(0xffffffffu, s, 2);
            q += __shfl_xor_sync(0xffffffffu, q, 2);
            if ((lane & 3) == 0) {
                int oc = ocb + mt*16 + g + h2*8;
                sp[oc*4 + (wid & 3)] = s;
                sq[oc*4 + (wid & 3)] = q;
            }
        }
    }
    __syncthreads();
    if (tid < 128) {
        float S = sp[tid*4] + sp[tid*4+1] + sp[tid*4+2] + sp[tid*4+3];
        float Q = sq[tid*4] + sq[tid*4+1] + sq[tid*4+2] + sq[tid*4+3];
        g_p1s[tid*256 + blockIdx.x] = S;
        g_p1q[tid*256 + blockIdx.x] = Q;
    }
}

// ---------------- reduce kernels for BN stats --------------------------------
__global__ __launch_bounds__(256) void k_red1() {
    __shared__ float ss[256], qq[256];
    int ch = blockIdx.x, tid = threadIdx.x;
    ss[tid] = g_p1s[ch*256 + tid];
    qq[tid] = g_p1q[ch*256 + tid];
    __syncthreads();
    for (int o = 128; o > 0; o >>= 1) {
        if (tid < o) { ss[tid] += ss[tid+o]; qq[tid] += qq[tid+o]; }
        __syncthreads();
    }
    if (tid == 0) {
        float mean = ss[0] * (1.f/32768.f);
        float var  = qq[0] * (1.f/32768.f) - mean*mean;
        g_s1[ch]      = mean;
        g_s1[CH + ch] = rsqrtf(var + 1e-5f);
    }
}
__global__ __launch_bounds__(128) void k_red2() {
    int ch = threadIdx.x;
    float s = 0.f, q = 0.f;
#pragma unroll
    for (int b = 0; b < BB; b++) {
        s += g_p2s[b*CH + ch];
        q += g_p2q[b*CH + ch];
    }
    float mean = s * (1.f/32768.f);
    float var  = q * (1.f/32768.f) - mean*mean;
    g_s2[ch]      = mean;
    g_s2[CH + ch] = rsqrtf(var + 1e-5f);
}

// ---------------- K7: fused bn1 + gelu + depthwise2 + stats2 -----------------
__global__ __launch_bounds__(256) void k_bngelu_dw2(const float* __restrict__ g,
                                                    const float* __restrict__ bv,
                                                    const float* __restrict__ w,
                                                    const float* __restrict__ bias) {
    __shared__ float T[66*68];
    __shared__ float rs[256], rq[256];
    int tid = threadIdx.x;
    int blk = blockIdx.x;          // (b, ch): 8*128
    int ch = blk & 127;
    float scale = g_s1[CH + ch] * g[ch];
    float shift = bv[ch] - g_s1[ch] * scale;
    const float* src = g_d + (size_t)blk*HW;

    for (int e = tid; e < 66*66; e += 256) {
        int r = e/66, c = e - (e/66)*66;
        int rr = r - 1, cc = c - 1;
        float v = 0.f;
        if ((unsigned)rr < 64u && (unsigned)cc < 64u) {
            float xn = src[rr*64 + cc] * scale + shift;
            v = 0.5f * xn * (1.f + erff(xn * 0.70710678118654752f));
        }
        T[r*68 + c] = v;
    }
    __syncthreads();

    const float* wc = w + ch*9;
    float w0 = wc[0], w1 = wc[1], w2 = wc[2], w3 = wc[3], w4 = wc[4],
          w5 = wc[5], w6 = wc[6], w7 = wc[7], w8 = wc[8];
    float bb = bias[ch];
    float* dst = g_u + (size_t)blk*HW;
    float s = 0.f, q = 0.f;
#pragma unroll
    for (int i = 0; i < 16; i++) {
        int px = i*256 + tid;
        int r = px >> 6, c = px & 63;
        const float* t0 = T + r*68 + c;
        float v = bb
            + w0*t0[0]     + w1*t0[1]     + w2*t0[2]
            + w3*t0[68]    + w4*t0[69]    + w5*t0[70]
            + w6*t0[136]   + w7*t0[137]   + w8*t0[138];
        dst[px] = v;
        s += v;
        q += v*v;
    }
    rs[tid] = s; rq[tid] = q;
    __syncthreads();
    for (int o = 128; o > 0; o >>= 1) {
        if (tid < o) { rs[tid] += rs[tid+o]; rq[tid] += rq[tid+o]; }
        __syncthreads();
    }
    if (tid == 0) { g_p2s[blk] = rs[0]; g_p2q[blk] = rq[0]; }
}

// ---------------- K9: bn2 + relu -> out (float4) -----------------------------
__global__ __launch_bounds__(256) void k_bn2relu(const float* __restrict__ g,
                                                 const float* __restrict__ bv,
                                                 float* __restrict__ out) {
    int i = blockIdx.x * 256 + threadIdx.x;
    if (i >= BB*CH*HW/4) return;
    int ch = ((i << 2) >> 12) & (CH-1);
    float scale = g_s2[CH + ch] * g[ch];
    float shift = bv[ch] - g_s2[ch] * scale;
    float4 v = *(const float4*)&g_u[(size_t)i*4];
    float4 o;
    o.x = fmaxf(v.x*scale + shift, 0.f);
    o.y = fmaxf(v.y*scale + shift, 0.f);
    o.z = fmaxf(v.z*scale + shift, 0.f);
    o.w = fmaxf(v.w*scale + shift, 0.f);
    *(float4*)&out[(size_t)i*4] = o;
}

// ---------------- launch ----------------------------------------------------
extern "C" void kernel_launch(void* const* d_in, const int* in_sizes, int n_in,
                              void* d_out, int out_size) {
    const float* x1      = (const float*)d_in[0];
    const float* x2      = (const float*)d_in[1];
    const float* dw1_w   = (const float*)d_in[2];
    const float* dw1_b   = (const float*)d_in[3];
    const float* pw_w    = (const float*)d_in[4];
    const float* pw_b    = (const float*)d_in[5];
    const float* p_w     = (const float*)d_in[6];
    const float* p_b     = (const float*)d_in[7];
    const float* m_w     = (const float*)d_in[8];
    const float* m_b     = (const float*)d_in[9];
    const float* dcn_w   = (const float*)d_in[10];
    const float* bn1_g   = (const float*)d_in[11];
    const float* bn1_b   = (const float*)d_in[12];
    const float* dw2_w   = (const float*)d_in[13];
    const float* dw2_b   = (const float*)d_in[14];
    const float* bn2_g   = (const float*)d_in[15];
    const float* bn2_b   = (const float*)d_in[16];
    float* out = (float*)d_out;

    cudaFuncSetAttribute(k_dgemm_tc,   cudaFuncAttributeMaxDynamicSharedMemorySize, SMEM_DG);
    cudaFuncSetAttribute(k_pw_tc,      cudaFuncAttributeMaxDynamicSharedMemorySize, SMEM_PW);
    cudaFuncSetAttribute(k_offmask_tc, cudaFuncAttributeMaxDynamicSharedMemorySize, SMEM_OM);

    int prep_items = 18*16384 + 4*16384 + 18*4096;
    k_prep <<<(prep_items + 255)/256, 256>>>(dcn_w, pw_w, p_w, m_w);
    k_updw1<<<BB*CC, 256>>>(x1, x2, dw1_w, dw1_b);
    k_pw_tc<<<PP/128, 256, SMEM_PW>>>(pw_b);
    k_offmask_tc<<<PP/128, 256, SMEM_OM>>>(p_b, m_b);
    k_dgemm_tc<<<PP/128, 256, SMEM_DG>>>();
    k_red1<<<CH, 256>>>();
    k_bngelu_dw2<<<BB*CH, 256>>>(bn1_g, bn1_b, dw2_w, dw2_b);
    k_red2<<<1, 128>>>();
    k_bn2relu<<<(BB*CH*HW/4 + 255)/256, 256>>>(bn2_g, bn2_b, out);
}

// round 10
// speedup vs baseline: 1.0348x; 1.0348x over previous
#include <cuda_runtime.h>
#include <cuda_bf16.h>
#include <math.h>
#include <cstdint>

#define BB 8
#define CH 128
#define CC 256
#define HW 4096
#define PP 32768      // BB*HW
#define KBIG 1152     // 128 ic * 9 taps

// ---------------- scratch (static device globals; no runtime alloc) --------
static __device__ float  g_h1 [BB*CC*HW];     // fused upcat+depthwise1 out
static __device__ float  g_h  [BB*CH*HW];     // pointwise out
static __device__ float  g_offb[BB*18*HW];    // offsets
static __device__ float  g_mb [BB*9*HW];      // modulation (sigmoid)
static __device__ float  g_d  [BB*CH*HW];     // deform conv out
static __device__ float  g_u  [BB*CH*HW];     // depthwise2 out
static __device__ float  g_p1s[CH*256];       // dgemm per-CTA channel sums
static __device__ float  g_p1q[CH*256];       // dgemm per-CTA channel sumsq
static __device__ float  g_p2s[BB*CH];        // dw2 per-CTA sums
static __device__ float  g_p2q[BB*CH];        // dw2 per-CTA sumsq
static __device__ __nv_bfloat16 g_wA [18*16384];  // dcn w: hi+lo SW128 images
static __device__ __nv_bfloat16 g_pwA[4*16384];   // pw w: hi+lo SW128 images
static __device__ __nv_bfloat16 g_omA[18*4096];   // off+mask w: hi+lo images

#define SW128(o)   ((o) ^ (((o) >> 3) & 0x70))

__device__ __forceinline__ uint32_t smem_u32(const void* p) {
    uint32_t a;
    asm("{ .reg .u64 t; cvta.to.shared.u64 t, %1; cvt.u32.u64 %0, t; }"
        : "=r"(a) : "l"(p));
    return a;
}
__device__ __forceinline__ void ldmx4(uint32_t* r, uint32_t addr) {
    asm volatile("ldmatrix.sync.aligned.m8n8.x4.shared.b16 {%0,%1,%2,%3}, [%4];"
                 : "=r"(r[0]), "=r"(r[1]), "=r"(r[2]), "=r"(r[3]) : "r"(addr));
}
__device__ __forceinline__ void mma_bf16(float* d, const uint32_t* a,
                                         uint32_t b0, uint32_t b1) {
    asm volatile("mma.sync.aligned.m16n8k16.row.col.f32.bf16.bf16.f32 "
                 "{%0,%1,%2,%3}, {%4,%5,%6,%7}, {%8,%9}, {%0,%1,%2,%3};"
                 : "+f"(d[0]), "+f"(d[1]), "+f"(d[2]), "+f"(d[3])
                 : "r"(a[0]), "r"(a[1]), "r"(a[2]), "r"(a[3]), "r"(b0), "r"(b1));
}
__device__ __forceinline__ void split_store(unsigned char* hi, unsigned char* lo,
                                            uint32_t off, float v0, float v1) {
    __nv_bfloat16 h0 = __float2bfloat16(v0);
    __nv_bfloat16 h1 = __float2bfloat16(v1);
    __nv_bfloat16 l0 = __float2bfloat16(v0 - __bfloat162float(h0));
    __nv_bfloat16 l1 = __float2bfloat16(v1 - __bfloat162float(h1));
    *(uint32_t*)(hi + off) = ((uint32_t)__bfloat16_as_ushort(h1) << 16) | __bfloat16_as_ushort(h0);
    *(uint32_t*)(lo + off) = ((uint32_t)__bfloat16_as_ushort(l1) << 16) | __bfloat16_as_ushort(l0);
}
__device__ __forceinline__ void hi_store(unsigned char* hi, uint32_t off,
                                         float v0, float v1) {
    __nv_bfloat16 h0 = __float2bfloat16(v0);
    __nv_bfloat16 h1 = __float2bfloat16(v1);
    *(uint32_t*)(hi + off) = ((uint32_t)__bfloat16_as_ushort(h1) << 16) | __bfloat16_as_ushort(h0);
}

// ---------------- K0: weight prep (hi/lo split + SW128 images) --------------
__global__ __launch_bounds__(256) void k_prep(const float* __restrict__ dcn_w,
                                              const float* __restrict__ pw_w,
                                              const float* __restrict__ p_w,
                                              const float* __restrict__ m_w) {
    int i = blockIdx.x * 256 + threadIdx.x;
    if (i < 18*16384) {
        int c = i >> 14, r = i & 16383;
        int s = r >> 13, e = r & 8191;
        int oc = e >> 6, ic = e & 63;
        int tap = c >> 1, ichalf = c & 1;
        float val = dcn_w[oc*KBIG + (ichalf*64 + ic)*9 + tap];
        __nv_bfloat16 hi = __float2bfloat16(val);
        __nv_bfloat16 out = s ? __float2bfloat16(val - __bfloat162float(hi)) : hi;
        g_wA[(size_t)c*16384 + s*8192 + (SW128((uint32_t)(oc*128 + ic*2)) >> 1)] = out;
        return;
    }
    i -= 18*16384;
    if (i < 4*16384) {
        int c = i >> 14, r = i & 16383;
        int s = r >> 13, e = r & 8191;
        int oc = e >> 6, ic = e & 63;
        float val = pw_w[oc*CC + c*64 + ic];
        __nv_bfloat16 hi = __float2bfloat16(val);
        __nv_bfloat16 out = s ? __float2bfloat16(val - __bfloat162float(hi)) : hi;
        g_pwA[(size_t)c*16384 + s*8192 + (SW128((uint32_t)(oc*128 + ic*2)) >> 1)] = out;
        return;
    }
    i -= 4*16384;
    if (i < 18*4096) {
        int c = i >> 12, r = i & 4095;
        int s = r >> 11, e = r & 2047;
        int oc = e >> 6, ic = e & 63;
        int tap = c >> 1, ichalf = c & 1;
        int icg = ichalf*64 + ic;
        float val = 0.f;
        if (oc < 18)      val = p_w[oc*KBIG + icg*9 + tap];
        else if (oc < 27) val = m_w[(oc-18)*KBIG + icg*9 + tap];
        __nv_bfloat16 hi = __float2bfloat16(val);
        __nv_bfloat16 out = s ? __float2bfloat16(val - __bfloat162float(hi)) : hi;
        g_omA[(size_t)c*4096 + s*2048 + (SW128((uint32_t)(oc*128 + ic*2)) >> 1)] = out;
    }
}

// ---------------- K1: fused bilinear-up2x + concat + depthwise1 -------------
__global__ __launch_bounds__(256) void k_updw1(const float* __restrict__ x1,
                                               const float* __restrict__ x2,
                                               const float* __restrict__ w,
                                               const float* __restrict__ bias) {
    __shared__ float T[66*68];
    __shared__ float X1[32*33];
    int tid = threadIdx.x;
    int blk = blockIdx.x;
    int b = blk >> 8, ch = blk & 255;

    if (ch < CH) {
        const float* img = x2 + (size_t)(b*CH + ch)*HW;
        for (int e = tid; e < 66*66; e += 256) {
            int r = e/66, c = e - (e/66)*66;
            int rr = r - 1, cc = c - 1;
            T[r*68 + c] = ((unsigned)rr < 64u && (unsigned)cc < 64u) ? img[rr*64 + cc] : 0.f;
        }
    } else {
        const float* img = x1 + ((size_t)(b*CH + ch - CH))*1024;
        for (int e = tid; e < 1024; e += 256)
            X1[(e >> 5)*33 + (e & 31)] = img[e];
        __syncthreads();
        for (int e = tid; e < 66*66; e += 256) {
            int r = e/66, c = e - (e/66)*66;
            int rr = r - 1, cc = c - 1;
            float v = 0.f;
            if ((unsigned)rr < 64u && (unsigned)cc < 64u) {
                float sr = (float)rr * (31.0f/63.0f);
                float sc = (float)cc * (31.0f/63.0f);
                int i0 = min((int)sr, 30);
                int j0 = min((int)sc, 30);
                float ty = sr - (float)i0;
                float tx = sc - (float)j0;
                float a00 = X1[i0*33 + j0],     a10 = X1[(i0+1)*33 + j0];
                float a01 = X1[i0*33 + j0 + 1], a11 = X1[(i0+1)*33 + j0 + 1];
                v = (a00*(1.f-ty) + a10*ty)*(1.f-tx) + (a01*(1.f-ty) + a11*ty)*tx;
            }
            T[r*68 + c] = v;
        }
    }
    __syncthreads();

    const float* wc = w + ch*9;
    float w0 = wc[0], w1 = wc[1], w2 = wc[2], w3 = wc[3], w4 = wc[4],
          w5 = wc[5], w6 = wc[6], w7 = wc[7], w8 = wc[8];
    float bb = bias[ch];
    float* dst = g_h1 + (size_t)blk*HW;
#pragma unroll
    for (int i = 0; i < 16; i++) {
        int px = i*256 + tid;
        int r = px >> 6, c = px & 63;
        const float* t0 = T + r*68 + c;
        dst[px] = bb
            + w0*t0[0]     + w1*t0[1]     + w2*t0[2]
            + w3*t0[68]    + w4*t0[69]    + w5*t0[70]
            + w6*t0[136]   + w7*t0[137]   + w8*t0[138];
    }
}

// ---------------- K3: pointwise 256->128 via mma.sync bf16x3 ----------------
#define SMEM_PW (2*65536)
__device__ __forceinline__ void pw_build(unsigned char* nb, int b, int c,
                                         int hw0, int tid) {
    float4* dstA = (float4*)nb;
    const float4* srcA = (const float4*)((const unsigned char*)g_pwA + (size_t)c*32768);
#pragma unroll
    for (int i = 0; i < 8; i++) dstA[tid + i*256] = srcA[tid + i*256];
    int pxB  = tid & 127;
    int half = tid >> 7;
    const float* img = g_h1 + ((size_t)(b*CC + c*64 + half*32))*HW + hw0 + pxB;
    unsigned char* bhi = nb + 32768;
    unsigned char* blo = bhi + 16384;
#pragma unroll
    for (int ip = 0; ip < 16; ip++) {
        float v0 = img[0]; img += HW;
        float v1 = img[0]; img += HW;
        split_store(bhi, blo, SW128((uint32_t)(pxB*128 + (half*32 + ip*2)*2)), v0, v1);
    }
}

__global__ __launch_bounds__(256, 1) void k_pw_tc(const float* __restrict__ bias) {
    extern __shared__ __align__(1024) unsigned char smem[];
    uint32_t sb = smem_u32(smem);
    int tid  = threadIdx.x;
    int lane = tid & 31;
    int wid  = tid >> 5;
    int pxg0 = blockIdx.x * 128;
    int b   = pxg0 >> 12;
    int hw0 = pxg0 & 4095;

    int ocb  = (wid >> 2) * 64;
    int pxb  = (wid & 3) * 32;
    int lrow = lane & 15;
    int lkh  = (lane >> 4) * 16;

    pw_build(smem, b, 0, hw0, tid);
    __syncthreads();

    float acc[4][4][4];
#pragma unroll
    for (int mt = 0; mt < 4; mt++)
#pragma unroll
        for (int nt = 0; nt < 4; nt++)
#pragma unroll
            for (int q = 0; q < 4; q++) acc[mt][nt][q] = 0.f;

    for (int c = 0; c < 4; c++) {
        int p = c & 1;
        uint32_t tb = sb + p*65536;
#pragma unroll
        for (int ks = 0; ks < 4; ks++) {
            int kb = ks*32 + lkh;
            uint32_t ah[4][4], al[4][4], bb[2][4];
#pragma unroll
            for (int mt = 0; mt < 4; mt++)
                ldmx4(ah[mt], tb + SW128((uint32_t)((ocb + mt*16 + lrow)*128 + kb)));
#pragma unroll
            for (int ntp = 0; ntp < 2; ntp++)
                ldmx4(bb[ntp], tb + 32768 + SW128((uint32_t)((pxb + ntp*16 + lrow)*128 + kb)));
#pragma unroll
            for (int mt = 0; mt < 4; mt++)
#pragma unroll
                for (int nt = 0; nt < 4; nt++)
                    mma_bf16(acc[mt][nt], ah[mt], bb[nt>>1][nt&1], bb[nt>>1][(nt&1)+2]);
#pragma unroll
            for (int mt = 0; mt < 4; mt++)
                ldmx4(al[mt], tb + 16384 + SW128((uint32_t)((ocb + mt*16 + lrow)*128 + kb)));
#pragma unroll
            for (int mt = 0; mt < 4; mt++)
#pragma unroll
                for (int nt = 0; nt < 4; nt++)
                    mma_bf16(acc[mt][nt], al[mt], bb[nt>>1][nt&1], bb[nt>>1][(nt&1)+2]);
#pragma unroll
            for (int ntp = 0; ntp < 2; ntp++)
                ldmx4(bb[ntp], tb + 49152 + SW128((uint32_t)((pxb + ntp*16 + lrow)*128 + kb)));
#pragma unroll
            for (int mt = 0; mt < 4; mt++)
#pragma unroll
                for (int nt = 0; nt < 4; nt++)
                    mma_bf16(acc[mt][nt], ah[mt], bb[nt>>1][nt&1], bb[nt>>1][(nt&1)+2]);
        }
        if (c < 3) pw_build(smem + (1-p)*65536, b, c + 1, hw0, tid);
        __syncthreads();
    }

    int g  = lane >> 2;
    int cx = (lane & 3) * 2;
#pragma unroll
    for (int mt = 0; mt < 4; mt++) {
#pragma unroll
        for (int nt = 0; nt < 4; nt++) {
            int oc = ocb + mt*16 + g;
            int px = pxb + nt*8 + cx;
            float b0 = bias[oc], b1 = bias[oc + 8];
            float* d0 = g_h + ((size_t)(b*CH + oc))*HW + hw0 + px;
            float* d1 = g_h + ((size_t)(b*CH + oc + 8))*HW + hw0 + px;
            *(float2*)d0 = make_float2(acc[mt][nt][0] + b0, acc[mt][nt][1] + b0);
            *(float2*)d1 = make_float2(acc[mt][nt][2] + b1, acc[mt][nt][3] + b1);
        }
    }
}

// ---------------- K4: offset+mask conv via mma.sync (A hi+lo, B hi only) ----
// 9 stages of K=128 (one tap, both ic halves).
// buf: A0hi 4K | A0lo 4K | A1hi 4K | A1lo 4K | B0 16K | B1 16K = 48KB
#define SM_NOFF  0
#define SM_OMT   5120
#define OM_BUF   49152
#define SMEM_OM  (SM_OMT + 2*OM_BUF)

__device__ __forceinline__ void om_stage(unsigned char* nb, const int* noff,
                                         int b, int c9, int pxB, int half, int tid) {
    float4* dstA = (float4*)nb;
    const float4* srcA = (const float4*)((const unsigned char*)g_omA + (size_t)c9*16384);
#pragma unroll
    for (int i = 0; i < 4; i++) dstA[tid + i*256] = srcA[tid + i*256];
    int idx = noff[c9*128 + pxB];   // tap = c9, same for both ic halves
#pragma unroll
    for (int sub = 0; sub < 2; sub++) {
        const float* img = g_h + ((size_t)(b*CH + sub*64 + half*32))*HW;
        unsigned char* bhi = nb + 16384 + sub*16384;
#pragma unroll
        for (int ip = 0; ip < 16; ip++) {
            float v0 = (idx >= 0) ? img[idx] : 0.f; img += HW;
            float v1 = (idx >= 0) ? img[idx] : 0.f; img += HW;
            hi_store(bhi, SW128((uint32_t)(pxB*128 + (half*32 + ip*2)*2)), v0, v1);
        }
    }
}

__global__ __launch_bounds__(256, 2) void k_offmask_tc(const float* __restrict__ pb,
                                                       const float* __restrict__ mb) {
    extern __shared__ __align__(1024) unsigned char smem[];
    uint32_t sb = smem_u32(smem);
    int* noff = (int*)(smem + SM_NOFF);
    int tid  = threadIdx.x;
    int lane = tid & 31;
    int wid  = tid >> 5;
    int pxg0 = blockIdx.x * 128;
    int b   = pxg0 >> 12;
    int hw0 = pxg0 & 4095;

    int pxB  = tid & 127;
    int half = tid >> 7;
    int pxw  = wid * 16;
    int lrow = lane & 15;
    int lkh  = (lane >> 4) * 16;

    for (int e = tid; e < 1152; e += 256) {
        int t = e >> 7, h = e & 127;
        int hw = hw0 + h;
        int r = hw >> 6, c = hw & 63;
        int dy = t/3 - 1, dx = t%3 - 1;
        int rr = r + dy, cc = c + dx;
        noff[e] = ((unsigned)rr < 64u && (unsigned)cc < 64u) ? (rr*64 + cc) : -1;
    }
    __syncthreads();

    om_stage(smem + SM_OMT, noff, b, 0, pxB, half, tid);
    __syncthreads();

    float acc[2][2][4];
#pragma unroll
    for (int mt = 0; mt < 2; mt++)
#pragma unroll
        for (int nt = 0; nt < 2; nt++)
#pragma unroll
            for (int q = 0; q < 4; q++) acc[mt][nt][q] = 0.f;

    for (int c9 = 0; c9 < 9; c9++) {
        int p = c9 & 1;
        uint32_t tb = sb + SM_OMT + p*OM_BUF;
#pragma unroll
        for (int sub = 0; sub < 2; sub++) {
            uint32_t ta = tb + sub*8192;
            uint32_t tbB = tb + 16384 + sub*16384;
#pragma unroll
            for (int ks = 0; ks < 4; ks++) {
                int kb = ks*32 + lkh;
                uint32_t ah[2][4], al[2][4], bh[4];
#pragma unroll
                for (int mt = 0; mt < 2; mt++)
                    ldmx4(ah[mt], ta + SW128((uint32_t)((mt*16 + lrow)*128 + kb)));
                ldmx4(bh, tbB + SW128((uint32_t)((pxw + lrow)*128 + kb)));
#pragma unroll
                for (int mt = 0; mt < 2; mt++)
#pragma unroll
                    for (int nt = 0; nt < 2; nt++)
                        mma_bf16(acc[mt][nt], ah[mt], bh[nt], bh[nt+2]);
#pragma unroll
                for (int mt = 0; mt < 2; mt++)
                    ldmx4(al[mt], ta + 4096 + SW128((uint32_t)((mt*16 + lrow)*128 + kb)));
#pragma unroll
                for (int mt = 0; mt < 2; mt++)
#pragma unroll
                    for (int nt = 0; nt < 2; nt++)
                        mma_bf16(acc[mt][nt], al[mt], bh[nt], bh[nt+2]);
            }
        }
        if (c9 < 8)
            om_stage(smem + SM_OMT + (1-p)*OM_BUF, noff, b, c9 + 1, pxB, half, tid);
        __syncthreads();
    }

    int g  = lane >> 2;
    int cx = (lane & 3) * 2;
#pragma unroll
    for (int mt = 0; mt < 2; mt++) {
#pragma unroll
        for (int nt = 0; nt < 2; nt++) {
            int px = hw0 + pxw + nt*8 + cx;
#pragma unroll
            for (int h2 = 0; h2 < 2; h2++) {
                int oc = mt*16 + g + h2*8;
                float v0 = acc[mt][nt][h2*2], v1 = acc[mt][nt][h2*2 + 1];
                if (oc < 18) {
                    float bbv = pb[oc];
                    float* d = g_offb + (size_t)(b*18 + oc)*HW + px;
                    *(float2*)d = make_float2(v0 + bbv, v1 + bbv);
                } else if (oc < 27) {
                    float bbv = mb[oc - 18];
                    float* d = g_mb + (size_t)(b*9 + oc - 18)*HW + px;
                    *(float2*)d = make_float2(1.f/(1.f + expf(-(v0 + bbv))),
                                              1.f/(1.f + expf(-(v1 + bbv))));
                }
            }
        }
    }
}

// ---------------- K5: deform conv via mma.sync bf16x3 + stats epilogue ------
#define SM_SI    0
#define SM_SW    18432
#define SM_TILE  36864
#define SMEM_DG  (SM_TILE + 2*65536)

__device__ __forceinline__ float dsample(const float* img, int4 id, float4 w) {
    float v = 0.f;
    if (id.x >= 0) v += w.x * img[id.x];
    if (id.y >= 0) v += w.y * img[id.y];
    if (id.z >= 0) v += w.z * img[id.z];
    if (id.w >= 0) v += w.w * img[id.w];
    return v;
}

__global__ __launch_bounds__(256, 1) void k_dgemm_tc() {
    extern __shared__ __align__(1024) unsigned char smem[];
    uint32_t sb = smem_u32(smem);
    int tid  = threadIdx.x;
    int lane = tid & 31;
    int wid  = tid >> 5;
    int pxg0 = blockIdx.x * 128;
    int b   = pxg0 >> 12;
    int hw0 = pxg0 & 4095;

    int4*   si = (int4*)(smem + SM_SI);
    float4* sw = (float4*)(smem + SM_SW);

    for (int e = tid; e < 1152; e += 256) {
        int n = e >> 7, h = e & 127;
        int hw = hw0 + h;
        int r = hw >> 6, c = hw & 63;
        float ox = g_offb[(size_t)(b*18 + n)*HW + hw];
        float oy = g_offb[(size_t)(b*18 + 9 + n)*HW + hw];
        float px = (float)(r + 1) + (float)(n/3 - 1) + ox;
        float py = (float)(c + 1) + (float)(n%3 - 1) + oy;
        float fx = floorf(px), fy = floorf(py);
        float qx0 = fminf(fmaxf(fx,       0.f), 65.f);
        float qx1 = fminf(fmaxf(fx + 1.f, 0.f), 65.f);
        float qy0 = fminf(fmaxf(fy,       0.f), 65.f);
        float qy1 = fminf(fmaxf(fy + 1.f, 0.f), 65.f);
        float pxc = fminf(fmaxf(px, 0.f), 65.f);
        float pyc = fminf(fmaxf(py, 0.f), 65.f);
        float glt = (1.f + (qx0 - pxc)) * (1.f + (qy0 - pyc));
        float grb = (1.f - (qx1 - pxc)) * (1.f - (qy1 - pyc));
        float glb = (1.f + (qx0 - pxc)) * (1.f - (qy1 - pyc));
        float grt = (1.f - (qx1 - pxc)) * (1.f + (qy0 - pyc));
        float mod = g_mb[(size_t)(b*9 + n)*HW + hw];
        int ix0 = (int)qx0, ix1 = (int)qx1, iy0 = (int)qy0, iy1 = (int)qy1;
#define ENC(qx,qy) (((qx)>=1 && (qx)<=64 && (qy)>=1 && (qy)<=64) ? (((qx)-1)*64 + ((qy)-1)) : -1)
        si[e] = make_int4(ENC(ix0,iy0), ENC(ix1,iy1), ENC(ix0,iy1), ENC(ix1,iy0));
#undef ENC
        sw[e] = make_float4(glt*mod, grb*mod, glb*mod, grt*mod);
    }
    __syncthreads();

    int pxB  = tid & 127;
    int half = tid >> 7;
    int ocb  = (wid >> 2) * 64;
    int pxb  = (wid & 3) * 32;
    int lrow = lane & 15;
    int lkh  = (lane >> 4) * 16;

    {
        float4* dstA = (float4*)(smem + SM_TILE);
        const float4* srcA = (const float4*)((const unsigned char*)g_wA);
#pragma unroll
        for (int i = 0; i < 8; i++) dstA[tid + i*256] = srcA[tid + i*256];
        int4   id = si[pxB];
        float4 wc = sw[pxB];
        const float* img = g_h + ((size_t)(b*CH + half*32))*HW;
        unsigned char* bhi = smem + SM_TILE + 32768;
        unsigned char* blo = bhi + 16384;
#pragma unroll
        for (int ip = 0; ip < 16; ip++) {
            float v0 = dsample(img, id, wc); img += HW;
            float v1 = dsample(img, id, wc); img += HW;
            split_store(bhi, blo, SW128((uint32_t)(pxB*128 + (half*32 + ip*2)*2)), v0, v1);
        }
    }
    __syncthreads();

    float acc[4][4][4];
#pragma unroll
    for (int mt = 0; mt < 4; mt++)
#pragma unroll
        for (int nt = 0; nt < 4; nt++)
#pragma unroll
            for (int q = 0; q < 4; q++) acc[mt][nt][q] = 0.f;

    for (int c = 0; c < 18; c++) {
        int p = c & 1;
        uint32_t tb = sb + SM_TILE + p*65536;
#pragma unroll
        for (int ks = 0; ks < 4; ks++) {
            int kb = ks*32 + lkh;
            uint32_t ah[4][4], al[4][4], bb[2][4];
#pragma unroll
            for (int mt = 0; mt < 4; mt++)
                ldmx4(ah[mt], tb + SW128((uint32_t)((ocb + mt*16 + lrow)*128 + kb)));
#pragma unroll
            for (int ntp = 0; ntp < 2; ntp++)
                ldmx4(bb[ntp], tb + 32768 + SW128((uint32_t)((pxb + ntp*16 + lrow)*128 + kb)));
#pragma unroll
            for (int mt = 0; mt < 4; mt++)
#pragma unroll
                for (int nt = 0; nt < 4; nt++)
                    mma_bf16(acc[mt][nt], ah[mt], bb[nt>>1][nt&1], bb[nt>>1][(nt&1)+2]);
#pragma unroll
            for (int mt = 0; mt < 4; mt++)
                ldmx4(al[mt], tb + 16384 + SW128((uint32_t)((ocb + mt*16 + lrow)*128 + kb)));
#pragma unroll
            for (int mt = 0; mt < 4; mt++)
#pragma unroll
                for (int nt = 0; nt < 4; nt++)
                    mma_bf16(acc[mt][nt], al[mt], bb[nt>>1][nt&1], bb[nt>>1][(nt&1)+2]);
#pragma unroll
            for (int ntp = 0; ntp < 2; ntp++)
                ldmx4(bb[ntp], tb + 49152 + SW128((uint32_t)((pxb + ntp*16 + lrow)*128 + kb)));
#pragma unroll
            for (int mt = 0; mt < 4; mt++)
#pragma unroll
                for (int nt = 0; nt < 4; nt++)
                    mma_bf16(acc[mt][nt], ah[mt], bb[nt>>1][nt&1], bb[nt>>1][(nt&1)+2]);
        }
        if (c < 17) {
            int cn = c + 1;
            unsigned char* nb = smem + SM_TILE + (1-p)*65536;
            float4* dstA = (float4*)nb;
            const float4* srcA = (const float4*)((const unsigned char*)g_wA + (size_t)cn*32768);
#pragma unroll
            for (int i = 0; i < 8; i++) dstA[tid + i*256] = srcA[tid + i*256];
            int tap = cn >> 1, ichalf = cn & 1;
            int m = tap*128 + pxB;
            int4   id = si[m];
            float4 wc = sw[m];
            const float* img = g_h + ((size_t)(b*CH + ichalf*64 + half*32))*HW;
            unsigned char* bhi = nb + 32768;
            unsigned char* blo = bhi + 16384;
#pragma unroll
            for (int ip = 0; ip < 16; ip++) {
                float v0 = dsample(img, id, wc); img += HW;
                float v1 = dsample(img, id, wc); img += HW;
                split_store(bhi, blo, SW128((uint32_t)(pxB*128 + (half*32 + ip*2)*2)), v0, v1);
            }
        }
        __syncthreads();
    }

    int g  = lane >> 2;
    int cx = (lane & 3) * 2;
#pragma unroll
    for (int mt = 0; mt < 4; mt++) {
#pragma unroll
        for (int nt = 0; nt < 4; nt++) {
            int oc = ocb + mt*16 + g;
            int px = pxb + nt*8 + cx;
            float* d0 = g_d + ((size_t)(b*CH + oc))*HW + hw0 + px;
            float* d1 = g_d + ((size_t)(b*CH + oc + 8))*HW + hw0 + px;
            *(float2*)d0 = make_float2(acc[mt][nt][0], acc[mt][nt][1]);
            *(float2*)d1 = make_float2(acc[mt][nt][2], acc[mt][nt][3]);
        }
    }

    // ---- BN1 stats epilogue: per-CTA per-channel (sum, sumsq) ----
    float* sp = (float*)smem;          // [128][4]
    float* sq = sp + 512;              // [128][4]
    __syncthreads();
#pragma unroll
    for (int mt = 0; mt < 4; mt++) {
#pragma unroll
        for (int h2 = 0; h2 < 2; h2++) {
            float s = 0.f, q = 0.f;
#pragma unroll
            for (int nt = 0; nt < 4; nt++) {
                float v0 = acc[mt][nt][h2*2], v1 = acc[mt][nt][h2*2 + 1];
                s += v0 + v1;
                q += v0*v0 + v1*v1;
            }
            s += __shfl_xor_sync(0xffffffffu, s, 1);
            q += __shfl_xor_sync(0xffffffffu, q, 1);
            s += __shfl_xor_sync(0xffffffffu, s, 2);
            q += __shfl_xor_sync(0xffffffffu, q, 2);
            if ((lane & 3) == 0) {
                int oc = ocb + mt*16 + g + h2*8;
                sp[oc*4 + (wid & 3)] = s;
                sq[oc*4 + (wid & 3)] = q;
            }
        }
    }
    __syncthreads();
    if (tid < 128) {
        float S = sp[tid*4] + sp[tid*4+1] + sp[tid*4+2] + sp[tid*4+3];
        float Q = sq[tid*4] + sq[tid*4+1] + sq[tid*4+2] + sq[tid*4+3];
        g_p1s[tid*256 + blockIdx.x] = S;
        g_p1q[tid*256 + blockIdx.x] = Q;
    }
}

// ---------------- K7: fused red1 + bn1 + gelu + depthwise2 + stats2 ---------
__global__ __launch_bounds__(256) void k_bngelu_dw2(const float* __restrict__ g,
                                                    const float* __restrict__ bv,
                                                    const float* __restrict__ w,
                                                    const float* __restrict__ bias) {
    __shared__ float T[66*68];
    __shared__ float rs[256], rq[256];
    __shared__ float stat[2];
    int tid = threadIdx.x;
    int blk = blockIdx.x;          // (b, ch): 8*128
    int ch = blk & 127;

    // fold of k_red1: reduce this channel's 256 dgemm partials
    rs[tid] = g_p1s[ch*256 + tid];
    rq[tid] = g_p1q[ch*256 + tid];
    __syncthreads();
    for (int o = 128; o > 0; o >>= 1) {
        if (tid < o) { rs[tid] += rs[tid+o]; rq[tid] += rq[tid+o]; }
        __syncthreads();
    }
    if (tid == 0) {
        float mean = rs[0] * (1.f/32768.f);
        float var  = rq[0] * (1.f/32768.f) - mean*mean;
        stat[0] = mean;
        stat[1] = rsqrtf(var + 1e-5f);
    }
    __syncthreads();
    float scale = stat[1] * g[ch];
    float shift = bv[ch] - stat[0] * scale;
    const float* src = g_d + (size_t)blk*HW;

    for (int e = tid; e < 66*66; e += 256) {
        int r = e/66, c = e - (e/66)*66;
        int rr = r - 1, cc = c - 1;
        float v = 0.f;
        if ((unsigned)rr < 64u && (unsigned)cc < 64u) {
            float xn = src[rr*64 + cc] * scale + shift;
            v = 0.5f * xn * (1.f + erff(xn * 0.70710678118654752f));
        }
        T[r*68 + c] = v;
    }
    __syncthreads();

    const float* wc = w + ch*9;
    float w0 = wc[0], w1 = wc[1], w2 = wc[2], w3 = wc[3], w4 = wc[4],
          w5 = wc[5], w6 = wc[6], w7 = wc[7], w8 = wc[8];
    float bb = bias[ch];
    float* dst = g_u + (size_t)blk*HW;
    float s = 0.f, q = 0.f;
#pragma unroll
    for (int i = 0; i < 16; i++) {
        int px = i*256 + tid;
        int r = px >> 6, c = px & 63;
        const float* t0 = T + r*68 + c;
        float v = bb
            + w0*t0[0]     + w1*t0[1]     + w2*t0[2]
            + w3*t0[68]    + w4*t0[69]    + w5*t0[70]
            + w6*t0[136]   + w7*t0[137]   + w8*t0[138];
        dst[px] = v;
        s += v;
        q += v*v;
    }
    rs[tid] = s; rq[tid] = q;
    __syncthreads();
    for (int o = 128; o > 0; o >>= 1) {
        if (tid < o) { rs[tid] += rs[tid+o]; rq[tid] += rq[tid+o]; }
        __syncthreads();
    }
    if (tid == 0) { g_p2s[blk] = rs[0]; g_p2q[blk] = rq[0]; }
}

// ---------------- K9: fused red2 + bn2 + relu -> out (float4) ----------------
__global__ __launch_bounds__(256) void k_bn2relu(const float* __restrict__ g,
                                                 const float* __restrict__ bv,
                                                 float* __restrict__ out) {
    __shared__ float stat[2];
    int i = blockIdx.x * 256 + threadIdx.x;      // float4 index
    int ch = ((blockIdx.x * 1024) >> 12) & (CH-1);
    if (threadIdx.x == 0) {
        float s = 0.f, q = 0.f;
#pragma unroll
        for (int b = 0; b < BB; b++) {
            s += g_p2s[b*CH + ch];
            q += g_p2q[b*CH + ch];
        }
        float mean = s * (1.f/32768.f);
        float var  = q * (1.f/32768.f) - mean*mean;
        stat[0] = mean;
        stat[1] = rsqrtf(var + 1e-5f);
    }
    __syncthreads();
    if (i >= BB*CH*HW/4) return;
    float scale = stat[1] * g[ch];
    float shift = bv[ch] - stat[0] * scale;
    float4 v = *(const float4*)&g_u[(size_t)i*4];
    float4 o;
    o.x = fmaxf(v.x*scale + shift, 0.f);
    o.y = fmaxf(v.y*scale + shift, 0.f);
    o.z = fmaxf(v.z*scale + shift, 0.f);
    o.w = fmaxf(v.w*scale + shift, 0.f);
    *(float4*)&out[(size_t)i*4] = o;
}

// ---------------- launch ----------------------------------------------------
extern "C" void kernel_launch(void* const* d_in, const int* in_sizes, int n_in,
                              void* d_out, int out_size) {
    const float* x1      = (const float*)d_in[0];
    const float* x2      = (const float*)d_in[1];
    const float* dw1_w   = (const float*)d_in[2];
    const float* dw1_b   = (const float*)d_in[3];
    const float* pw_w    = (const float*)d_in[4];
    const float* pw_b    = (const float*)d_in[5];
    const float* p_w     = (const float*)d_in[6];
    const float* p_b     = (const float*)d_in[7];
    const float* m_w     = (const float*)d_in[8];
    const float* m_b     = (const float*)d_in[9];
    const float* dcn_w   = (const float*)d_in[10];
    const float* bn1_g   = (const float*)d_in[11];
    const float* bn1_b   = (const float*)d_in[12];
    const float* dw2_w   = (const float*)d_in[13];
    const float* dw2_b   = (const float*)d_in[14];
    const float* bn2_g   = (const float*)d_in[15];
    const float* bn2_b   = (const float*)d_in[16];
    float* out = (float*)d_out;

    cudaFuncSetAttribute(k_dgemm_tc,   cudaFuncAttributeMaxDynamicSharedMemorySize, SMEM_DG);
    cudaFuncSetAttribute(k_pw_tc,      cudaFuncAttributeMaxDynamicSharedMemorySize, SMEM_PW);
    cudaFuncSetAttribute(k_offmask_tc, cudaFuncAttributeMaxDynamicSharedMemorySize, SMEM_OM);

    int prep_items = 18*16384 + 4*16384 + 18*4096;
    k_prep <<<(prep_items + 255)/256, 256>>>(dcn_w, pw_w, p_w, m_w);
    k_updw1<<<BB*CC, 256>>>(x1, x2, dw1_w, dw1_b);
    k_pw_tc<<<PP/128, 256, SMEM_PW>>>(pw_b);
    k_offmask_tc<<<PP/128, 256, SMEM_OM>>>(p_b, m_b);
    k_dgemm_tc<<<PP/128, 256, SMEM_DG>>>();
    k_bngelu_dw2<<<BB*CH, 256>>>(bn1_g, bn1_b, dw2_w, dw2_b);
    k_bn2relu<<<BB*CH*HW/4/256, 256>>>(bn2_g, bn2_b, out);  // 4096 blocks
}

// round 11
// speedup vs baseline: 1.0606x; 1.0249x over previous
#include <cuda_runtime.h>
#include <cuda_bf16.h>
#include <math.h>
#include <cstdint>

#define BB 8
#define CH 128
#define CC 256
#define HW 4096
#define PP 32768      // BB*HW
#define KBIG 1152     // 128 ic * 9 taps

// ---------------- scratch (static device globals; no runtime alloc) --------
static __device__ float  g_h1 [BB*CC*HW];     // fused upcat+depthwise1 out
static __device__ float  g_h  [BB*CH*HW];     // pointwise out
static __device__ float  g_offb[BB*18*HW];    // offsets
static __device__ float  g_mb [BB*9*HW];      // modulation (sigmoid)
static __device__ float  g_d  [BB*CH*HW];     // deform conv out
static __device__ float  g_u  [BB*CH*HW];     // depthwise2 out
static __device__ float  g_p1s[CH*256];       // dgemm per-CTA channel sums
static __device__ float  g_p1q[CH*256];       // dgemm per-CTA channel sumsq
static __device__ float  g_p2s[BB*CH];        // dw2 per-CTA sums
static __device__ float  g_p2q[BB*CH];        // dw2 per-CTA sumsq
static __device__ __nv_bfloat16 g_wA [18*16384];  // dcn w: hi+lo SW128 images
static __device__ __nv_bfloat16 g_pwA[4*16384];   // pw w: hi+lo SW128 images
static __device__ __nv_bfloat16 g_omA[18*4096];   // off+mask w: hi+lo images

#define SW128(o)   ((o) ^ (((o) >> 3) & 0x70))

__device__ __forceinline__ uint32_t smem_u32(const void* p) {
    uint32_t a;
    asm("{ .reg .u64 t; cvta.to.shared.u64 t, %1; cvt.u32.u64 %0, t; }"
        : "=r"(a) : "l"(p));
    return a;
}
__device__ __forceinline__ void ldmx4(uint32_t* r, uint32_t addr) {
    asm volatile("ldmatrix.sync.aligned.m8n8.x4.shared.b16 {%0,%1,%2,%3}, [%4];"
                 : "=r"(r[0]), "=r"(r[1]), "=r"(r[2]), "=r"(r[3]) : "r"(addr));
}
__device__ __forceinline__ void mma_bf16(float* d, const uint32_t* a,
                                         uint32_t b0, uint32_t b1) {
    asm volatile("mma.sync.aligned.m16n8k16.row.col.f32.bf16.bf16.f32 "
                 "{%0,%1,%2,%3}, {%4,%5,%6,%7}, {%8,%9}, {%0,%1,%2,%3};"
                 : "+f"(d[0]), "+f"(d[1]), "+f"(d[2]), "+f"(d[3])
                 : "r"(a[0]), "r"(a[1]), "r"(a[2]), "r"(a[3]), "r"(b0), "r"(b1));
}
__device__ __forceinline__ uint32_t pack_bf2(float v0, float v1) {
    __nv_bfloat16 h0 = __float2bfloat16(v0);
    __nv_bfloat16 h1 = __float2bfloat16(v1);
    return ((uint32_t)__bfloat16_as_ushort(h1) << 16) | __bfloat16_as_ushort(h0);
}
// pack 4 consecutive-ic values into one 8-byte STS (hi image only)
__device__ __forceinline__ void hi_store4(unsigned char* hi, uint32_t off,
                                          const float* v) {
    uint2 w;
    w.x = pack_bf2(v[0], v[1]);
    w.y = pack_bf2(v[2], v[3]);
    *(uint2*)(hi + off) = w;
}
// hi + lo split, 4 ics per STS.64
__device__ __forceinline__ void split_store4(unsigned char* hi, unsigned char* lo,
                                             uint32_t off, const float* v) {
    float r[4];
#pragma unroll
    for (int j = 0; j < 4; j++)
        r[j] = v[j] - __bfloat162float(__float2bfloat16(v[j]));
    uint2 wh, wl;
    wh.x = pack_bf2(v[0], v[1]);
    wh.y = pack_bf2(v[2], v[3]);
    wl.x = pack_bf2(r[0], r[1]);
    wl.y = pack_bf2(r[2], r[3]);
    *(uint2*)(hi + off) = wh;
    *(uint2*)(lo + off) = wl;
}

// ---------------- K0: weight prep (hi/lo split + SW128 images) --------------
__global__ __launch_bounds__(256) void k_prep(const float* __restrict__ dcn_w,
                                              const float* __restrict__ pw_w,
                                              const float* __restrict__ p_w,
                                              const float* __restrict__ m_w) {
    int i = blockIdx.x * 256 + threadIdx.x;
    if (i < 18*16384) {
        int c = i >> 14, r = i & 16383;
        int s = r >> 13, e = r & 8191;
        int oc = e >> 6, ic = e & 63;
        int tap = c >> 1, ichalf = c & 1;
        float val = dcn_w[oc*KBIG + (ichalf*64 + ic)*9 + tap];
        __nv_bfloat16 hi = __float2bfloat16(val);
        __nv_bfloat16 out = s ? __float2bfloat16(val - __bfloat162float(hi)) : hi;
        g_wA[(size_t)c*16384 + s*8192 + (SW128((uint32_t)(oc*128 + ic*2)) >> 1)] = out;
        return;
    }
    i -= 18*16384;
    if (i < 4*16384) {
        int c = i >> 14, r = i & 16383;
        int s = r >> 13, e = r & 8191;
        int oc = e >> 6, ic = e & 63;
        float val = pw_w[oc*CC + c*64 + ic];
        __nv_bfloat16 hi = __float2bfloat16(val);
        __nv_bfloat16 out = s ? __float2bfloat16(val - __bfloat162float(hi)) : hi;
        g_pwA[(size_t)c*16384 + s*8192 + (SW128((uint32_t)(oc*128 + ic*2)) >> 1)] = out;
        return;
    }
    i -= 4*16384;
    if (i < 18*4096) {
        int c = i >> 12, r = i & 4095;
        int s = r >> 11, e = r & 2047;
        int oc = e >> 6, ic = e & 63;
        int tap = c >> 1, ichalf = c & 1;
        int icg = ichalf*64 + ic;
        float val = 0.f;
        if (oc < 18)      val = p_w[oc*KBIG + icg*9 + tap];
        else if (oc < 27) val = m_w[(oc-18)*KBIG + icg*9 + tap];
        __nv_bfloat16 hi = __float2bfloat16(val);
        __nv_bfloat16 out = s ? __float2bfloat16(val - __bfloat162float(hi)) : hi;
        g_omA[(size_t)c*4096 + s*2048 + (SW128((uint32_t)(oc*128 + ic*2)) >> 1)] = out;
    }
}

// ---------------- K1: fused bilinear-up2x + concat + depthwise1 -------------
__global__ __launch_bounds__(256) void k_updw1(const float* __restrict__ x1,
                                               const float* __restrict__ x2,
                                               const float* __restrict__ w,
                                               const float* __restrict__ bias) {
    __shared__ float T[66*68];
    __shared__ float X1[32*33];
    int tid = threadIdx.x;
    int blk = blockIdx.x;
    int b = blk >> 8, ch = blk & 255;

    if (ch < CH) {
        const float* img = x2 + (size_t)(b*CH + ch)*HW;
        for (int e = tid; e < 66*66; e += 256) {
            int r = e/66, c = e - (e/66)*66;
            int rr = r - 1, cc = c - 1;
            T[r*68 + c] = ((unsigned)rr < 64u && (unsigned)cc < 64u) ? img[rr*64 + cc] : 0.f;
        }
    } else {
        const float* img = x1 + ((size_t)(b*CH + ch - CH))*1024;
        for (int e = tid; e < 1024; e += 256)
            X1[(e >> 5)*33 + (e & 31)] = img[e];
        __syncthreads();
        for (int e = tid; e < 66*66; e += 256) {
            int r = e/66, c = e - (e/66)*66;
            int rr = r - 1, cc = c - 1;
            float v = 0.f;
            if ((unsigned)rr < 64u && (unsigned)cc < 64u) {
                float sr = (float)rr * (31.0f/63.0f);
                float sc = (float)cc * (31.0f/63.0f);
                int i0 = min((int)sr, 30);
                int j0 = min((int)sc, 30);
                float ty = sr - (float)i0;
                float tx = sc - (float)j0;
                float a00 = X1[i0*33 + j0],     a10 = X1[(i0+1)*33 + j0];
                float a01 = X1[i0*33 + j0 + 1], a11 = X1[(i0+1)*33 + j0 + 1];
                v = (a00*(1.f-ty) + a10*ty)*(1.f-tx) + (a01*(1.f-ty) + a11*ty)*tx;
            }
            T[r*68 + c] = v;
        }
    }
    __syncthreads();

    const float* wc = w + ch*9;
    float w0 = wc[0], w1 = wc[1], w2 = wc[2], w3 = wc[3], w4 = wc[4],
          w5 = wc[5], w6 = wc[6], w7 = wc[7], w8 = wc[8];
    float bb = bias[ch];
    float* dst = g_h1 + (size_t)blk*HW;
#pragma unroll
    for (int i = 0; i < 16; i++) {
        int px = i*256 + tid;
        int r = px >> 6, c = px & 63;
        const float* t0 = T + r*68 + c;
        dst[px] = bb
            + w0*t0[0]     + w1*t0[1]     + w2*t0[2]
            + w3*t0[68]    + w4*t0[69]    + w5*t0[70]
            + w6*t0[136]   + w7*t0[137]   + w8*t0[138];
    }
}

// ---------------- K3: pointwise 256->128 via mma.sync bf16x3 ----------------
#define SMEM_PW (2*65536)
__device__ __forceinline__ void pw_build(unsigned char* nb, int b, int c,
                                         int hw0, int tid) {
    float4* dstA = (float4*)nb;
    const float4* srcA = (const float4*)((const unsigned char*)g_pwA + (size_t)c*32768);
#pragma unroll
    for (int i = 0; i < 8; i++) dstA[tid + i*256] = srcA[tid + i*256];
    int pxB  = tid & 127;
    int half = tid >> 7;
    const float* img = g_h1 + ((size_t)(b*CC + c*64 + half*32))*HW + hw0 + pxB;
    unsigned char* bhi = nb + 32768;
    unsigned char* blo = bhi + 16384;
#pragma unroll
    for (int ip = 0; ip < 8; ip++) {
        float v[4];
#pragma unroll
        for (int j = 0; j < 4; j++) { v[j] = img[0]; img += HW; }
        split_store4(bhi, blo, SW128((uint32_t)(pxB*128 + (half*32 + ip*4)*2)), v);
    }
}

__global__ __launch_bounds__(256, 1) void k_pw_tc(const float* __restrict__ bias) {
    extern __shared__ __align__(1024) unsigned char smem[];
    uint32_t sb = smem_u32(smem);
    int tid  = threadIdx.x;
    int lane = tid & 31;
    int wid  = tid >> 5;
    int pxg0 = blockIdx.x * 128;
    int b   = pxg0 >> 12;
    int hw0 = pxg0 & 4095;

    int ocb  = (wid >> 2) * 64;
    int pxb  = (wid & 3) * 32;
    int lrow = lane & 15;
    int lkh  = (lane >> 4) * 16;

    pw_build(smem, b, 0, hw0, tid);
    __syncthreads();

    float acc[4][4][4];
#pragma unroll
    for (int mt = 0; mt < 4; mt++)
#pragma unroll
        for (int nt = 0; nt < 4; nt++)
#pragma unroll
            for (int q = 0; q < 4; q++) acc[mt][nt][q] = 0.f;

    for (int c = 0; c < 4; c++) {
        int p = c & 1;
        uint32_t tb = sb + p*65536;
#pragma unroll
        for (int ks = 0; ks < 4; ks++) {
            int kb = ks*32 + lkh;
            uint32_t ah[4][4], al[4][4], bb[2][4];
#pragma unroll
            for (int mt = 0; mt < 4; mt++)
                ldmx4(ah[mt], tb + SW128((uint32_t)((ocb + mt*16 + lrow)*128 + kb)));
#pragma unroll
            for (int ntp = 0; ntp < 2; ntp++)
                ldmx4(bb[ntp], tb + 32768 + SW128((uint32_t)((pxb + ntp*16 + lrow)*128 + kb)));
#pragma unroll
            for (int mt = 0; mt < 4; mt++)
#pragma unroll
                for (int nt = 0; nt < 4; nt++)
                    mma_bf16(acc[mt][nt], ah[mt], bb[nt>>1][nt&1], bb[nt>>1][(nt&1)+2]);
#pragma unroll
            for (int mt = 0; mt < 4; mt++)
                ldmx4(al[mt], tb + 16384 + SW128((uint32_t)((ocb + mt*16 + lrow)*128 + kb)));
#pragma unroll
            for (int mt = 0; mt < 4; mt++)
#pragma unroll
                for (int nt = 0; nt < 4; nt++)
                    mma_bf16(acc[mt][nt], al[mt], bb[nt>>1][nt&1], bb[nt>>1][(nt&1)+2]);
#pragma unroll
            for (int ntp = 0; ntp < 2; ntp++)
                ldmx4(bb[ntp], tb + 49152 + SW128((uint32_t)((pxb + ntp*16 + lrow)*128 + kb)));
#pragma unroll
            for (int mt = 0; mt < 4; mt++)
#pragma unroll
                for (int nt = 0; nt < 4; nt++)
                    mma_bf16(acc[mt][nt], ah[mt], bb[nt>>1][nt&1], bb[nt>>1][(nt&1)+2]);
        }
        if (c < 3) pw_build(smem + (1-p)*65536, b, c + 1, hw0, tid);
        __syncthreads();
    }

    int g  = lane >> 2;
    int cx = (lane & 3) * 2;
#pragma unroll
    for (int mt = 0; mt < 4; mt++) {
#pragma unroll
        for (int nt = 0; nt < 4; nt++) {
            int oc = ocb + mt*16 + g;
            int px = pxb + nt*8 + cx;
            float b0 = bias[oc], b1 = bias[oc + 8];
            float* d0 = g_h + ((size_t)(b*CH + oc))*HW + hw0 + px;
            float* d1 = g_h + ((size_t)(b*CH + oc + 8))*HW + hw0 + px;
            *(float2*)d0 = make_float2(acc[mt][nt][0] + b0, acc[mt][nt][1] + b0);
            *(float2*)d1 = make_float2(acc[mt][nt][2] + b1, acc[mt][nt][3] + b1);
        }
    }
}

// ---------------- K4: offset+mask conv via mma.sync (A hi+lo, B hi only) ----
// R8 form: 18 stages of K=64; buf = Ahi 4K | Alo 4K | Bhi 16K = 24KB
#define SM_NOFF  0
#define SM_OMT   5120
#define OM_BUF   24576
#define SMEM_OM  (SM_OMT + 2*OM_BUF)

__device__ __forceinline__ void om_stage(unsigned char* nb, const int* noff,
                                         int b, int c, int pxB, int half, int tid) {
    float4* dstA = (float4*)nb;
    const float4* srcA = (const float4*)((const unsigned char*)g_omA + (size_t)c*8192);
#pragma unroll
    for (int i = 0; i < 2; i++) dstA[tid + i*256] = srcA[tid + i*256];
    int tap = c >> 1, ichalf = c & 1;
    int idx = noff[tap*128 + pxB];
    const float* img = g_h + ((size_t)(b*CH + ichalf*64 + half*32))*HW;
    unsigned char* bhi = nb + 8192;
#pragma unroll
    for (int ip = 0; ip < 8; ip++) {
        float v[4];
#pragma unroll
        for (int j = 0; j < 4; j++) {
            v[j] = (idx >= 0) ? img[idx] : 0.f;
            img += HW;
        }
        hi_store4(bhi, SW128((uint32_t)(pxB*128 + (half*32 + ip*4)*2)), v);
    }
}

__global__ __launch_bounds__(256, 3) void k_offmask_tc(const float* __restrict__ pb,
                                                       const float* __restrict__ mb) {
    extern __shared__ __align__(1024) unsigned char smem[];
    uint32_t sb = smem_u32(smem);
    int* noff = (int*)(smem + SM_NOFF);
    int tid  = threadIdx.x;
    int lane = tid & 31;
    int wid  = tid >> 5;
    int pxg0 = blockIdx.x * 128;
    int b   = pxg0 >> 12;
    int hw0 = pxg0 & 4095;

    int pxB  = tid & 127;
    int half = tid >> 7;
    int pxw  = wid * 16;
    int lrow = lane & 15;
    int lkh  = (lane >> 4) * 16;

    for (int e = tid; e < 1152; e += 256) {
        int t = e >> 7, h = e & 127;
        int hw = hw0 + h;
        int r = hw >> 6, c = hw & 63;
        int dy = t/3 - 1, dx = t%3 - 1;
        int rr = r + dy, cc = c + dx;
        noff[e] = ((unsigned)rr < 64u && (unsigned)cc < 64u) ? (rr*64 + cc) : -1;
    }
    __syncthreads();

    om_stage(smem + SM_OMT, noff, b, 0, pxB, half, tid);
    __syncthreads();

    float acc[2][2][4];
#pragma unroll
    for (int mt = 0; mt < 2; mt++)
#pragma unroll
        for (int nt = 0; nt < 2; nt++)
#pragma unroll
            for (int q = 0; q < 4; q++) acc[mt][nt][q] = 0.f;

    for (int c = 0; c < 18; c++) {
        int p = c & 1;
        uint32_t tb = sb + SM_OMT + p*OM_BUF;
#pragma unroll
        for (int ks = 0; ks < 4; ks++) {
            int kb = ks*32 + lkh;
            uint32_t ah[2][4], al[2][4], bh[4];
#pragma unroll
            for (int mt = 0; mt < 2; mt++)
                ldmx4(ah[mt], tb + SW128((uint32_t)((mt*16 + lrow)*128 + kb)));
            ldmx4(bh, tb + 8192 + SW128((uint32_t)((pxw + lrow)*128 + kb)));
#pragma unroll
            for (int mt = 0; mt < 2; mt++)
#pragma unroll
                for (int nt = 0; nt < 2; nt++)
                    mma_bf16(acc[mt][nt], ah[mt], bh[nt], bh[nt+2]);
#pragma unroll
            for (int mt = 0; mt < 2; mt++)
                ldmx4(al[mt], tb + 4096 + SW128((uint32_t)((mt*16 + lrow)*128 + kb)));
#pragma unroll
            for (int mt = 0; mt < 2; mt++)
#pragma unroll
                for (int nt = 0; nt < 2; nt++)
                    mma_bf16(acc[mt][nt], al[mt], bh[nt], bh[nt+2]);
        }
        if (c < 17)
            om_stage(smem + SM_OMT + (1-p)*OM_BUF, noff, b, c + 1, pxB, half, tid);
        __syncthreads();
    }

    int g  = lane >> 2;
    int cx = (lane & 3) * 2;
#pragma unroll
    for (int mt = 0; mt < 2; mt++) {
#pragma unroll
        for (int nt = 0; nt < 2; nt++) {
            int px = hw0 + pxw + nt*8 + cx;
#pragma unroll
            for (int h2 = 0; h2 < 2; h2++) {
                int oc = mt*16 + g + h2*8;
                float v0 = acc[mt][nt][h2*2], v1 = acc[mt][nt][h2*2 + 1];
                if (oc < 18) {
                    float bbv = pb[oc];
                    float* d = g_offb + (size_t)(b*18 + oc)*HW + px;
                    *(float2*)d = make_float2(v0 + bbv, v1 + bbv);
                } else if (oc < 27) {
                    float bbv = mb[oc - 18];
                    float* d = g_mb + (size_t)(b*9 + oc - 18)*HW + px;
                    *(float2*)d = make_float2(1.f/(1.f + expf(-(v0 + bbv))),
                                              1.f/(1.f + expf(-(v1 + bbv))));
                }
            }
        }
    }
}

// ---------------- K5: deform conv via mma.sync bf16x3 + stats epilogue ------
#define SM_SI    0
#define SM_SW    18432
#define SM_TILE  36864
#define SMEM_DG  (SM_TILE + 2*65536)

__device__ __forceinline__ float dsample(const float* img, int4 id, float4 w) {
    float v = 0.f;
    if (id.x >= 0) v += w.x * img[id.x];
    if (id.y >= 0) v += w.y * img[id.y];
    if (id.z >= 0) v += w.z * img[id.z];
    if (id.w >= 0) v += w.w * img[id.w];
    return v;
}

__device__ __forceinline__ void dg_build(unsigned char* nb, const int4* si,
                                         const float4* sw, int b, int c,
                                         int pxB, int half, int tid) {
    float4* dstA = (float4*)nb;
    const float4* srcA = (const float4*)((const unsigned char*)g_wA + (size_t)c*32768);
#pragma unroll
    for (int i = 0; i < 8; i++) dstA[tid + i*256] = srcA[tid + i*256];
    int tap = c >> 1, ichalf = c & 1;
    int m = tap*128 + pxB;
    int4   id = si[m];
    float4 wc = sw[m];
    const float* img = g_h + ((size_t)(b*CH + ichalf*64 + half*32))*HW;
    unsigned char* bhi = nb + 32768;
    unsigned char* blo = bhi + 16384;
#pragma unroll
    for (int ip = 0; ip < 8; ip++) {
        float v[4];
#pragma unroll
        for (int j = 0; j < 4; j++) {
            v[j] = dsample(img, id, wc);
            img += HW;
        }
        split_store4(bhi, blo, SW128((uint32_t)(pxB*128 + (half*32 + ip*4)*2)), v);
    }
}

__global__ __launch_bounds__(256, 1) void k_dgemm_tc() {
    extern __shared__ __align__(1024) unsigned char smem[];
    uint32_t sb = smem_u32(smem);
    int tid  = threadIdx.x;
    int lane = tid & 31;
    int wid  = tid >> 5;
    int pxg0 = blockIdx.x * 128;
    int b   = pxg0 >> 12;
    int hw0 = pxg0 & 4095;

    int4*   si = (int4*)(smem + SM_SI);
    float4* sw = (float4*)(smem + SM_SW);

    for (int e = tid; e < 1152; e += 256) {
        int n = e >> 7, h = e & 127;
        int hw = hw0 + h;
        int r = hw >> 6, c = hw & 63;
        float ox = g_offb[(size_t)(b*18 + n)*HW + hw];
        float oy = g_offb[(size_t)(b*18 + 9 + n)*HW + hw];
        float px = (float)(r + 1) + (float)(n/3 - 1) + ox;
        float py = (float)(c + 1) + (float)(n%3 - 1) + oy;
        float fx = floorf(px), fy = floorf(py);
        float qx0 = fminf(fmaxf(fx,       0.f), 65.f);
        float qx1 = fminf(fmaxf(fx + 1.f, 0.f), 65.f);
        float qy0 = fminf(fmaxf(fy,       0.f), 65.f);
        float qy1 = fminf(fmaxf(fy + 1.f, 0.f), 65.f);
        float pxc = fminf(fmaxf(px, 0.f), 65.f);
        float pyc = fminf(fmaxf(py, 0.f), 65.f);
        float glt = (1.f + (qx0 - pxc)) * (1.f + (qy0 - pyc));
        float grb = (1.f - (qx1 - pxc)) * (1.f - (qy1 - pyc));
        float glb = (1.f + (qx0 - pxc)) * (1.f - (qy1 - pyc));
        float grt = (1.f - (qx1 - pxc)) * (1.f + (qy0 - pyc));
        float mod = g_mb[(size_t)(b*9 + n)*HW + hw];
        int ix0 = (int)qx0, ix1 = (int)qx1, iy0 = (int)qy0, iy1 = (int)qy1;
#define ENC(qx,qy) (((qx)>=1 && (qx)<=64 && (qy)>=1 && (qy)<=64) ? (((qx)-1)*64 + ((qy)-1)) : -1)
        si[e] = make_int4(ENC(ix0,iy0), ENC(ix1,iy1), ENC(ix0,iy1), ENC(ix1,iy0));
#undef ENC
        sw[e] = make_float4(glt*mod, grb*mod, glb*mod, grt*mod);
    }
    __syncthreads();

    int pxB  = tid & 127;
    int half = tid >> 7;
    int ocb  = (wid >> 2) * 64;
    int pxb  = (wid & 3) * 32;
    int lrow = lane & 15;
    int lkh  = (lane >> 4) * 16;

    dg_build(smem + SM_TILE, si, sw, b, 0, pxB, half, tid);
    __syncthreads();

    float acc[4][4][4];
#pragma unroll
    for (int mt = 0; mt < 4; mt++)
#pragma unroll
        for (int nt = 0; nt < 4; nt++)
#pragma unroll
            for (int q = 0; q < 4; q++) acc[mt][nt][q] = 0.f;

    for (int c = 0; c < 18; c++) {
        int p = c & 1;
        uint32_t tb = sb + SM_TILE + p*65536;
#pragma unroll
        for (int ks = 0; ks < 4; ks++) {
            int kb = ks*32 + lkh;
            uint32_t ah[4][4], al[4][4], bb[2][4];
#pragma unroll
            for (int mt = 0; mt < 4; mt++)
                ldmx4(ah[mt], tb + SW128((uint32_t)((ocb + mt*16 + lrow)*128 + kb)));
#pragma unroll
            for (int ntp = 0; ntp < 2; ntp++)
                ldmx4(bb[ntp], tb + 32768 + SW128((uint32_t)((pxb + ntp*16 + lrow)*128 + kb)));
#pragma unroll
            for (int mt = 0; mt < 4; mt++)
#pragma unroll
                for (int nt = 0; nt < 4; nt++)
                    mma_bf16(acc[mt][nt], ah[mt], bb[nt>>1][nt&1], bb[nt>>1][(nt&1)+2]);
#pragma unroll
            for (int mt = 0; mt < 4; mt++)
                ldmx4(al[mt], tb + 16384 + SW128((uint32_t)((ocb + mt*16 + lrow)*128 + kb)));
#pragma unroll
            for (int mt = 0; mt < 4; mt++)
#pragma unroll
                for (int nt = 0; nt < 4; nt++)
                    mma_bf16(acc[mt][nt], al[mt], bb[nt>>1][nt&1], bb[nt>>1][(nt&1)+2]);
#pragma unroll
            for (int ntp = 0; ntp < 2; ntp++)
                ldmx4(bb[ntp], tb + 49152 + SW128((uint32_t)((pxb + ntp*16 + lrow)*128 + kb)));
#pragma unroll
            for (int mt = 0; mt < 4; mt++)
#pragma unroll
                for (int nt = 0; nt < 4; nt++)
                    mma_bf16(acc[mt][nt], ah[mt], bb[nt>>1][nt&1], bb[nt>>1][(nt&1)+2]);
        }
        if (c < 17)
            dg_build(smem + SM_TILE + (1-p)*65536, si, sw, b, c + 1, pxB, half, tid);
        __syncthreads();
    }

    int g  = lane >> 2;
    int cx = (lane & 3) * 2;
#pragma unroll
    for (int mt = 0; mt < 4; mt++) {
#pragma unroll
        for (int nt = 0; nt < 4; nt++) {
            int oc = ocb + mt*16 + g;
            int px = pxb + nt*8 + cx;
            float* d0 = g_d + ((size_t)(b*CH + oc))*HW + hw0 + px;
            float* d1 = g_d + ((size_t)(b*CH + oc + 8))*HW + hw0 + px;
            *(float2*)d0 = make_float2(acc[mt][nt][0], acc[mt][nt][1]);
            *(float2*)d1 = make_float2(acc[mt][nt][2], acc[mt][nt][3]);
        }
    }

    // ---- BN1 stats epilogue: per-CTA per-channel (sum, sumsq) ----
    float* sp = (float*)smem;          // [128][4]
    float* sq = sp + 512;              // [128][4]
    __syncthreads();
#pragma unroll
    for (int mt = 0; mt < 4; mt++) {
#pragma unroll
        for (int h2 = 0; h2 < 2; h2++) {
            float s = 0.f, q = 0.f;
#pragma unroll
            for (int nt = 0; nt < 4; nt++) {
                float v0 = acc[mt][nt][h2*2], v1 = acc[mt][nt][h2*2 + 1];
                s += v0 + v1;
                q += v0*v0 + v1*v1;
            }
            s += __shfl_xor_sync(0xffffffffu, s, 1);
            q += __shfl_xor_sync(0xffffffffu, q, 1);
            s += __shfl_xor_sync(0xffffffffu, s, 2);
            q += __shfl_xor_sync(0xffffffffu, q, 2);
            if ((lane & 3) == 0) {
                int oc = ocb + mt*16 + g + h2*8;
                sp[oc*4 + (wid & 3)] = s;
                sq[oc*4 + (wid & 3)] = q;
            }
        }
    }
    __syncthreads();
    if (tid < 128) {
        float S = sp[tid*4] + sp[tid*4+1] + sp[tid*4+2] + sp[tid*4+3];
        float Q = sq[tid*4] + sq[tid*4+1] + sq[tid*4+2] + sq[tid*4+3];
        g_p1s[tid*256 + blockIdx.x] = S;
        g_p1q[tid*256 + blockIdx.x] = Q;
    }
}

// ---------------- K7: fused red1 + bn1 + gelu + depthwise2 + stats2 ---------
__global__ __launch_bounds__(256) void k_bngelu_dw2(const float* __restrict__ g,
                                                    const float* __restrict__ bv,
                                                    const float* __restrict__ w,
                                                    const float* __restrict__ bias) {
    __shared__ float T[66*68];
    __shared__ float rs[256], rq[256];
    __shared__ float stat[2];
    int tid = threadIdx.x;
    int blk = blockIdx.x;          // (b, ch): 8*128
    int ch = blk & 127;

    rs[tid] = g_p1s[ch*256 + tid];
    rq[tid] = g_p1q[ch*256 + tid];
    __syncthreads();
    for (int o = 128; o > 0; o >>= 1) {
        if (tid < o) { rs[tid] += rs[tid+o]; rq[tid] += rq[tid+o]; }
        __syncthreads();
    }
    if (tid == 0) {
        float mean = rs[0] * (1.f/32768.f);
        float var  = rq[0] * (1.f/32768.f) - mean*mean;
        stat[0] = mean;
        stat[1] = rsqrtf(var + 1e-5f);
    }
    __syncthreads();
    float scale = stat[1] * g[ch];
    float shift = bv[ch] - stat[0] * scale;
    const float* src = g_d + (size_t)blk*HW;

    for (int e = tid; e < 66*66; e += 256) {
        int r = e/66, c = e - (e/66)*66;
        int rr = r - 1, cc = c - 1;
        float v = 0.f;
        if ((unsigned)rr < 64u && (unsigned)cc < 64u) {
            float xn = src[rr*64 + cc] * scale + shift;
            v = 0.5f * xn * (1.f + erff(xn * 0.70710678118654752f));
        }
        T[r*68 + c] = v;
    }
    __syncthreads();

    const float* wc = w + ch*9;
    float w0 = wc[0], w1 = wc[1], w2 = wc[2], w3 = wc[3], w4 = wc[4],
          w5 = wc[5], w6 = wc[6], w7 = wc[7], w8 = wc[8];
    float bb = bias[ch];
    float* dst = g_u + (size_t)blk*HW;
    float s = 0.f, q = 0.f;
#pragma unroll
    for (int i = 0; i < 16; i++) {
        int px = i*256 + tid;
        int r = px >> 6, c = px & 63;
        const float* t0 = T + r*68 + c;
        float v = bb
            + w0*t0[0]     + w1*t0[1]     + w2*t0[2]
            + w3*t0[68]    + w4*t0[69]    + w5*t0[70]
            + w6*t0[136]   + w7*t0[137]   + w8*t0[138];
        dst[px] = v;
        s += v;
        q += v*v;
    }
    rs[tid] = s; rq[tid] = q;
    __syncthreads();
    for (int o = 128; o > 0; o >>= 1) {
        if (tid < o) { rs[tid] += rs[tid+o]; rq[tid] += rq[tid+o]; }
        __syncthreads();
    }
    if (tid == 0) { g_p2s[blk] = rs[0]; g_p2q[blk] = rq[0]; }
}

// ---------------- K9: fused red2 + bn2 + relu -> out (float4) ----------------
__global__ __launch_bounds__(256) void k_bn2relu(const float* __restrict__ g,
                                                 const float* __restrict__ bv,
                                                 float* __restrict__ out) {
    __shared__ float stat[2];
    int i = blockIdx.x * 256 + threadIdx.x;      // float4 index
    int ch = ((blockIdx.x * 1024) >> 12) & (CH-1);
    if (threadIdx.x == 0) {
        float s = 0.f, q = 0.f;
#pragma unroll
        for (int b = 0; b < BB; b++) {
            s += g_p2s[b*CH + ch];
            q += g_p2q[b*CH + ch];
        }
        float mean = s * (1.f/32768.f);
        float var  = q * (1.f/32768.f) - mean*mean;
        stat[0] = mean;
        stat[1] = rsqrtf(var + 1e-5f);
    }
    __syncthreads();
    if (i >= BB*CH*HW/4) return;
    float scale = stat[1] * g[ch];
    float shift = bv[ch] - stat[0] * scale;
    float4 v = *(const float4*)&g_u[(size_t)i*4];
    float4 o;
    o.x = fmaxf(v.x*scale + shift, 0.f);
    o.y = fmaxf(v.y*scale + shift, 0.f);
    o.z = fmaxf(v.z*scale + shift, 0.f);
    o.w = fmaxf(v.w*scale + shift, 0.f);
    *(float4*)&out[(size_t)i*4] = o;
}

// ---------------- launch ----------------------------------------------------
extern "C" void kernel_launch(void* const* d_in, const int* in_sizes, int n_in,
                              void* d_out, int out_size) {
    const float* x1      = (const float*)d_in[0];
    const float* x2      = (const float*)d_in[1];
    const float* dw1_w   = (const float*)d_in[2];
    const float* dw1_b   = (const float*)d_in[3];
    const float* pw_w    = (const float*)d_in[4];
    const float* pw_b    = (const float*)d_in[5];
    const float* p_w     = (const float*)d_in[6];
    const float* p_b     = (const float*)d_in[7];
    const float* m_w     = (const float*)d_in[8];
    const float* m_b     = (const float*)d_in[9];
    const float* dcn_w   = (const float*)d_in[10];
    const float* bn1_g   = (const float*)d_in[11];
    const float* bn1_b   = (const float*)d_in[12];
    const float* dw2_w   = (const float*)d_in[13];
    const float* dw2_b   = (const float*)d_in[14];
    const float* bn2_g   = (const float*)d_in[15];
    const float* bn2_b   = (const float*)d_in[16];
    float* out = (float*)d_out;

    cudaFuncSetAttribute(k_dgemm_tc,   cudaFuncAttributeMaxDynamicSharedMemorySize, SMEM_DG);
    cudaFuncSetAttribute(k_pw_tc,      cudaFuncAttributeMaxDynamicSharedMemorySize, SMEM_PW);
    cudaFuncSetAttribute(k_offmask_tc, cudaFuncAttributeMaxDynamicSharedMemorySize, SMEM_OM);

    int prep_items = 18*16384 + 4*16384 + 18*4096;
    k_prep <<<(prep_items + 255)/256, 256>>>(dcn_w, pw_w, p_w, m_w);
    k_updw1<<<BB*CC, 256>>>(x1, x2, dw1_w, dw1_b);
    k_pw_tc<<<PP/128, 256, SMEM_PW>>>(pw_b);
    k_offmask_tc<<<PP/128, 256, SMEM_OM>>>(p_b, m_b);
    k_dgemm_tc<<<PP/128, 256, SMEM_DG>>>();
    k_bngelu_dw2<<<BB*CH, 256>>>(bn1_g, bn1_b, dw2_w, dw2_b);
    k_bn2relu<<<BB*CH*HW/4/256, 256>>>(bn2_g, bn2_b, out);  // 4096 blocks
}

// round 12
// speedup vs baseline: 1.2891x; 1.2155x over previous
#include <cuda_runtime.h>
#include <cuda_fp16.h>
#include <math.h>
#include <cstdint>

#define BB 8
#define CH 128
#define CC 256
#define HW 4096
#define PP 32768      // BB*HW
#define KBIG 1152     // 128 ic * 9 taps

// ---------------- scratch (static device globals; no runtime alloc) --------
static __device__ float  g_h1 [BB*CC*HW];     // fused upcat+depthwise1 out
static __device__ float  g_h  [BB*CH*HW];     // pointwise out
static __device__ float  g_offb[BB*18*HW];    // offsets
static __device__ float  g_mb [BB*9*HW];      // modulation (sigmoid)
static __device__ float  g_d  [BB*CH*HW];     // deform conv out
static __device__ float  g_u  [BB*CH*HW];     // depthwise2 out
static __device__ float  g_p1s[CH*256];       // dgemm per-CTA channel sums
static __device__ float  g_p1q[CH*256];       // dgemm per-CTA channel sumsq
static __device__ float  g_p2s[BB*CH];        // dw2 per-CTA sums
static __device__ float  g_p2q[BB*CH];        // dw2 per-CTA sumsq
static __device__ __half g_wA [18*16384];     // dcn w: hi+lo SW128 images (fp16)
static __device__ __half g_pwA[4*16384];      // pw w: hi+lo SW128 images
static __device__ __half g_omA[18*4096];      // off+mask w: hi+lo images

#define SW128(o)   ((o) ^ (((o) >> 3) & 0x70))

__device__ __forceinline__ uint32_t smem_u32(const void* p) {
    uint32_t a;
    asm("{ .reg .u64 t; cvta.to.shared.u64 t, %1; cvt.u32.u64 %0, t; }"
        : "=r"(a) : "l"(p));
    return a;
}
__device__ __forceinline__ void ldmx4(uint32_t* r, uint32_t addr) {
    asm volatile("ldmatrix.sync.aligned.m8n8.x4.shared.b16 {%0,%1,%2,%3}, [%4];"
                 : "=r"(r[0]), "=r"(r[1]), "=r"(r[2]), "=r"(r[3]) : "r"(addr));
}
__device__ __forceinline__ void mma_f16(float* d, const uint32_t* a,
                                        uint32_t b0, uint32_t b1) {
    asm volatile("mma.sync.aligned.m16n8k16.row.col.f32.f16.f16.f32 "
                 "{%0,%1,%2,%3}, {%4,%5,%6,%7}, {%8,%9}, {%0,%1,%2,%3};"
                 : "+f"(d[0]), "+f"(d[1]), "+f"(d[2]), "+f"(d[3])
                 : "r"(a[0]), "r"(a[1]), "r"(a[2]), "r"(a[3]), "r"(b0), "r"(b1));
}
__device__ __forceinline__ uint32_t pack_h2(float v0, float v1) {
    __half2 h = __floats2half2_rn(v0, v1);
    return *(uint32_t*)&h;
}
// pack 4 consecutive-ic fp16 values into one 8-byte STS
__device__ __forceinline__ void hi_store4(unsigned char* hi, uint32_t off,
                                          const float* v) {
    uint2 w;
    w.x = pack_h2(v[0], v[1]);
    w.y = pack_h2(v[2], v[3]);
    *(uint2*)(hi + off) = w;
}

// ---------------- K0: weight prep (fp16 hi/lo split + SW128 images) ---------
__global__ __launch_bounds__(256) void k_prep(const float* __restrict__ dcn_w,
                                              const float* __restrict__ pw_w,
                                              const float* __restrict__ p_w,
                                              const float* __restrict__ m_w) {
    int i = blockIdx.x * 256 + threadIdx.x;
    if (i < 18*16384) {
        int c = i >> 14, r = i & 16383;
        int s = r >> 13, e = r & 8191;
        int oc = e >> 6, ic = e & 63;
        int tap = c >> 1, ichalf = c & 1;
        float val = dcn_w[oc*KBIG + (ichalf*64 + ic)*9 + tap];
        __half hi = __float2half(val);
        __half out = s ? __float2half(val - __half2float(hi)) : hi;
        g_wA[(size_t)c*16384 + s*8192 + (SW128((uint32_t)(oc*128 + ic*2)) >> 1)] = out;
        return;
    }
    i -= 18*16384;
    if (i < 4*16384) {
        int c = i >> 14, r = i & 16383;
        int s = r >> 13, e = r & 8191;
        int oc = e >> 6, ic = e & 63;
        float val = pw_w[oc*CC + c*64 + ic];
        __half hi = __float2half(val);
        __half out = s ? __float2half(val - __half2float(hi)) : hi;
        g_pwA[(size_t)c*16384 + s*8192 + (SW128((uint32_t)(oc*128 + ic*2)) >> 1)] = out;
        return;
    }
    i -= 4*16384;
    if (i < 18*4096) {
        int c = i >> 12, r = i & 4095;
        int s = r >> 11, e = r & 2047;
        int oc = e >> 6, ic = e & 63;
        int tap = c >> 1, ichalf = c & 1;
        int icg = ichalf*64 + ic;
        float val = 0.f;
        if (oc < 18)      val = p_w[oc*KBIG + icg*9 + tap];
        else if (oc < 27) val = m_w[(oc-18)*KBIG + icg*9 + tap];
        __half hi = __float2half(val);
        __half out = s ? __float2half(val - __half2float(hi)) : hi;
        g_omA[(size_t)c*4096 + s*2048 + (SW128((uint32_t)(oc*128 + ic*2)) >> 1)] = out;
    }
}

// ---------------- K1: fused bilinear-up2x + concat + depthwise1 -------------
__global__ __launch_bounds__(256) void k_updw1(const float* __restrict__ x1,
                                               const float* __restrict__ x2,
                                               const float* __restrict__ w,
                                               const float* __restrict__ bias) {
    __shared__ float T[66*68];
    __shared__ float X1[32*33];
    int tid = threadIdx.x;
    int blk = blockIdx.x;
    int b = blk >> 8, ch = blk & 255;

    if (ch < CH) {
        const float* img = x2 + (size_t)(b*CH + ch)*HW;
        for (int e = tid; e < 66*66; e += 256) {
            int r = e/66, c = e - (e/66)*66;
            int rr = r - 1, cc = c - 1;
            T[r*68 + c] = ((unsigned)rr < 64u && (unsigned)cc < 64u) ? img[rr*64 + cc] : 0.f;
        }
    } else {
        const float* img = x1 + ((size_t)(b*CH + ch - CH))*1024;
        for (int e = tid; e < 1024; e += 256)
            X1[(e >> 5)*33 + (e & 31)] = img[e];
        __syncthreads();
        for (int e = tid; e < 66*66; e += 256) {
            int r = e/66, c = e - (e/66)*66;
            int rr = r - 1, cc = c - 1;
            float v = 0.f;
            if ((unsigned)rr < 64u && (unsigned)cc < 64u) {
                float sr = (float)rr * (31.0f/63.0f);
                float sc = (float)cc * (31.0f/63.0f);
                int i0 = min((int)sr, 30);
                int j0 = min((int)sc, 30);
                float ty = sr - (float)i0;
                float tx = sc - (float)j0;
                float a00 = X1[i0*33 + j0],     a10 = X1[(i0+1)*33 + j0];
                float a01 = X1[i0*33 + j0 + 1], a11 = X1[(i0+1)*33 + j0 + 1];
                v = (a00*(1.f-ty) + a10*ty)*(1.f-tx) + (a01*(1.f-ty) + a11*ty)*tx;
            }
            T[r*68 + c] = v;
        }
    }
    __syncthreads();

    const float* wc = w + ch*9;
    float w0 = wc[0], w1 = wc[1], w2 = wc[2], w3 = wc[3], w4 = wc[4],
          w5 = wc[5], w6 = wc[6], w7 = wc[7], w8 = wc[8];
    float bb = bias[ch];
    float* dst = g_h1 + (size_t)blk*HW;
#pragma unroll
    for (int i = 0; i < 16; i++) {
        int px = i*256 + tid;
        int r = px >> 6, c = px & 63;
        const float* t0 = T + r*68 + c;
        dst[px] = bb
            + w0*t0[0]     + w1*t0[1]     + w2*t0[2]
            + w3*t0[68]    + w4*t0[69]    + w5*t0[70]
            + w6*t0[136]   + w7*t0[137]   + w8*t0[138];
    }
}

// ---------------- K3: pointwise 256->128 via mma.sync fp16 (A hi+lo, B hi) --
// buf: Ahi 16K | Alo 16K | B 16K = 48KB
#define PW_BUF  49152
#define SMEM_PW (2*PW_BUF)
__device__ __forceinline__ void pw_build(unsigned char* nb, int b, int c,
                                         int hw0, int tid) {
    float4* dstA = (float4*)nb;
    const float4* srcA = (const float4*)((const unsigned char*)g_pwA + (size_t)c*32768);
#pragma unroll
    for (int i = 0; i < 8; i++) dstA[tid + i*256] = srcA[tid + i*256];
    int pxB  = tid & 127;
    int half = tid >> 7;
    const float* img = g_h1 + ((size_t)(b*CC + c*64 + half*32))*HW + hw0 + pxB;
    unsigned char* bhi = nb + 32768;
#pragma unroll
    for (int ip = 0; ip < 8; ip++) {
        float v[4];
#pragma unroll
        for (int j = 0; j < 4; j++) { v[j] = img[0]; img += HW; }
        hi_store4(bhi, SW128((uint32_t)(pxB*128 + (half*32 + ip*4)*2)), v);
    }
}

__global__ __launch_bounds__(256, 1) void k_pw_tc(const float* __restrict__ bias) {
    extern __shared__ __align__(1024) unsigned char smem[];
    uint32_t sb = smem_u32(smem);
    int tid  = threadIdx.x;
    int lane = tid & 31;
    int wid  = tid >> 5;
    int pxg0 = blockIdx.x * 128;
    int b   = pxg0 >> 12;
    int hw0 = pxg0 & 4095;

    int ocb  = (wid >> 2) * 64;
    int pxb  = (wid & 3) * 32;
    int lrow = lane & 15;
    int lkh  = (lane >> 4) * 16;

    pw_build(smem, b, 0, hw0, tid);
    __syncthreads();

    float acc[4][4][4];
#pragma unroll
    for (int mt = 0; mt < 4; mt++)
#pragma unroll
        for (int nt = 0; nt < 4; nt++)
#pragma unroll
            for (int q = 0; q < 4; q++) acc[mt][nt][q] = 0.f;

    for (int c = 0; c < 4; c++) {
        int p = c & 1;
        uint32_t tb = sb + p*PW_BUF;
#pragma unroll
        for (int ks = 0; ks < 4; ks++) {
            int kb = ks*32 + lkh;
            uint32_t ah[4][4], al[4][4], bb[2][4];
#pragma unroll
            for (int mt = 0; mt < 4; mt++)
                ldmx4(ah[mt], tb + SW128((uint32_t)((ocb + mt*16 + lrow)*128 + kb)));
#pragma unroll
            for (int ntp = 0; ntp < 2; ntp++)
                ldmx4(bb[ntp], tb + 32768 + SW128((uint32_t)((pxb + ntp*16 + lrow)*128 + kb)));
#pragma unroll
            for (int mt = 0; mt < 4; mt++)
#pragma unroll
                for (int nt = 0; nt < 4; nt++)
                    mma_f16(acc[mt][nt], ah[mt], bb[nt>>1][nt&1], bb[nt>>1][(nt&1)+2]);
#pragma unroll
            for (int mt = 0; mt < 4; mt++)
                ldmx4(al[mt], tb + 16384 + SW128((uint32_t)((ocb + mt*16 + lrow)*128 + kb)));
#pragma unroll
            for (int mt = 0; mt < 4; mt++)
#pragma unroll
                for (int nt = 0; nt < 4; nt++)
                    mma_f16(acc[mt][nt], al[mt], bb[nt>>1][nt&1], bb[nt>>1][(nt&1)+2]);
        }
        if (c < 3) pw_build(smem + (1-p)*PW_BUF, b, c + 1, hw0, tid);
        __syncthreads();
    }

    int g  = lane >> 2;
    int cx = (lane & 3) * 2;
#pragma unroll
    for (int mt = 0; mt < 4; mt++) {
#pragma unroll
        for (int nt = 0; nt < 4; nt++) {
            int oc = ocb + mt*16 + g;
            int px = pxb + nt*8 + cx;
            float b0 = bias[oc], b1 = bias[oc + 8];
            float* d0 = g_h + ((size_t)(b*CH + oc))*HW + hw0 + px;
            float* d1 = g_h + ((size_t)(b*CH + oc + 8))*HW + hw0 + px;
            *(float2*)d0 = make_float2(acc[mt][nt][0] + b0, acc[mt][nt][1] + b0);
            *(float2*)d1 = make_float2(acc[mt][nt][2] + b1, acc[mt][nt][3] + b1);
        }
    }
}

// ---------------- K4: offset+mask conv via mma.sync fp16 (A hi+lo, B hi) ----
// 18 stages of K=64; buf = Ahi 4K | Alo 4K | B 16K = 24KB
#define SM_NOFF  0
#define SM_OMT   5120
#define OM_BUF   24576
#define SMEM_OM  (SM_OMT + 2*OM_BUF)

__device__ __forceinline__ void om_stage(unsigned char* nb, const int* noff,
                                         int b, int c, int pxB, int half, int tid) {
    float4* dstA = (float4*)nb;
    const float4* srcA = (const float4*)((const unsigned char*)g_omA + (size_t)c*8192);
#pragma unroll
    for (int i = 0; i < 2; i++) dstA[tid + i*256] = srcA[tid + i*256];
    int tap = c >> 1, ichalf = c & 1;
    int idx = noff[tap*128 + pxB];
    const float* img = g_h + ((size_t)(b*CH + ichalf*64 + half*32))*HW;
    unsigned char* bhi = nb + 8192;
#pragma unroll
    for (int ip = 0; ip < 8; ip++) {
        float v[4];
#pragma unroll
        for (int j = 0; j < 4; j++) {
            v[j] = (idx >= 0) ? img[idx] : 0.f;
            img += HW;
        }
        hi_store4(bhi, SW128((uint32_t)(pxB*128 + (half*32 + ip*4)*2)), v);
    }
}

__global__ __launch_bounds__(256, 3) void k_offmask_tc(const float* __restrict__ pb,
                                                       const float* __restrict__ mb) {
    extern __shared__ __align__(1024) unsigned char smem[];
    uint32_t sb = smem_u32(smem);
    int* noff = (int*)(smem + SM_NOFF);
    int tid  = threadIdx.x;
    int lane = tid & 31;
    int wid  = tid >> 5;
    int pxg0 = blockIdx.x * 128;
    int b   = pxg0 >> 12;
    int hw0 = pxg0 & 4095;

    int pxB  = tid & 127;
    int half = tid >> 7;
    int pxw  = wid * 16;
    int lrow = lane & 15;
    int lkh  = (lane >> 4) * 16;

    for (int e = tid; e < 1152; e += 256) {
        int t = e >> 7, h = e & 127;
        int hw = hw0 + h;
        int r = hw >> 6, c = hw & 63;
        int dy = t/3 - 1, dx = t%3 - 1;
        int rr = r + dy, cc = c + dx;
        noff[e] = ((unsigned)rr < 64u && (unsigned)cc < 64u) ? (rr*64 + cc) : -1;
    }
    __syncthreads();

    om_stage(smem + SM_OMT, noff, b, 0, pxB, half, tid);
    __syncthreads();

    float acc[2][2][4];
#pragma unroll
    for (int mt = 0; mt < 2; mt++)
#pragma unroll
        for (int nt = 0; nt < 2; nt++)
#pragma unroll
            for (int q = 0; q < 4; q++) acc[mt][nt][q] = 0.f;

    for (int c = 0; c < 18; c++) {
        int p = c & 1;
        uint32_t tb = sb + SM_OMT + p*OM_BUF;
#pragma unroll
        for (int ks = 0; ks < 4; ks++) {
            int kb = ks*32 + lkh;
            uint32_t ah[2][4], al[2][4], bh[4];
#pragma unroll
            for (int mt = 0; mt < 2; mt++)
                ldmx4(ah[mt], tb + SW128((uint32_t)((mt*16 + lrow)*128 + kb)));
            ldmx4(bh, tb + 8192 + SW128((uint32_t)((pxw + lrow)*128 + kb)));
#pragma unroll
            for (int mt = 0; mt < 2; mt++)
#pragma unroll
                for (int nt = 0; nt < 2; nt++)
                    mma_f16(acc[mt][nt], ah[mt], bh[nt], bh[nt+2]);
#pragma unroll
            for (int mt = 0; mt < 2; mt++)
                ldmx4(al[mt], tb + 4096 + SW128((uint32_t)((mt*16 + lrow)*128 + kb)));
#pragma unroll
            for (int mt = 0; mt < 2; mt++)
#pragma unroll
                for (int nt = 0; nt < 2; nt++)
                    mma_f16(acc[mt][nt], al[mt], bh[nt], bh[nt+2]);
        }
        if (c < 17)
            om_stage(smem + SM_OMT + (1-p)*OM_BUF, noff, b, c + 1, pxB, half, tid);
        __syncthreads();
    }

    int g  = lane >> 2;
    int cx = (lane & 3) * 2;
#pragma unroll
    for (int mt = 0; mt < 2; mt++) {
#pragma unroll
        for (int nt = 0; nt < 2; nt++) {
            int px = hw0 + pxw + nt*8 + cx;
#pragma unroll
            for (int h2 = 0; h2 < 2; h2++) {
                int oc = mt*16 + g + h2*8;
                float v0 = acc[mt][nt][h2*2], v1 = acc[mt][nt][h2*2 + 1];
                if (oc < 18) {
                    float bbv = pb[oc];
                    float* d = g_offb + (size_t)(b*18 + oc)*HW + px;
                    *(float2*)d = make_float2(v0 + bbv, v1 + bbv);
                } else if (oc < 27) {
                    float bbv = mb[oc - 18];
                    float* d = g_mb + (size_t)(b*9 + oc - 18)*HW + px;
                    *(float2*)d = make_float2(1.f/(1.f + expf(-(v0 + bbv))),
                                              1.f/(1.f + expf(-(v1 + bbv))));
                }
            }
        }
    }
}

// ---------------- K5: deform conv via mma.sync fp16 (A hi+lo, B hi) ---------
// buf: Ahi 16K | Alo 16K | B 16K = 48KB
#define SM_SI    0
#define SM_SW    18432
#define SM_TILE  36864
#define DG_BUF   49152
#define SMEM_DG  (SM_TILE + 2*DG_BUF)

__device__ __forceinline__ float dsample(const float* img, int4 id, float4 w) {
    float v = 0.f;
    if (id.x >= 0) v += w.x * img[id.x];
    if (id.y >= 0) v += w.y * img[id.y];
    if (id.z >= 0) v += w.z * img[id.z];
    if (id.w >= 0) v += w.w * img[id.w];
    return v;
}

__device__ __forceinline__ void dg_build(unsigned char* nb, const int4* si,
                                         const float4* sw, int b, int c,
                                         int pxB, int half, int tid) {
    float4* dstA = (float4*)nb;
    const float4* srcA = (const float4*)((const unsigned char*)g_wA + (size_t)c*32768);
#pragma unroll
    for (int i = 0; i < 8; i++) dstA[tid + i*256] = srcA[tid + i*256];
    int tap = c >> 1, ichalf = c & 1;
    int m = tap*128 + pxB;
    int4   id = si[m];
    float4 wc = sw[m];
    const float* img = g_h + ((size_t)(b*CH + ichalf*64 + half*32))*HW;
    unsigned char* bhi = nb + 32768;
#pragma unroll
    for (int ip = 0; ip < 8; ip++) {
        float v[4];
#pragma unroll
        for (int j = 0; j < 4; j++) {
            v[j] = dsample(img, id, wc);
            img += HW;
        }
        hi_store4(bhi, SW128((uint32_t)(pxB*128 + (half*32 + ip*4)*2)), v);
    }
}

__global__ __launch_bounds__(256, 1) void k_dgemm_tc() {
    extern __shared__ __align__(1024) unsigned char smem[];
    uint32_t sb = smem_u32(smem);
    int tid  = threadIdx.x;
    int lane = tid & 31;
    int wid  = tid >> 5;
    int pxg0 = blockIdx.x * 128;
    int b   = pxg0 >> 12;
    int hw0 = pxg0 & 4095;

    int4*   si = (int4*)(smem + SM_SI);
    float4* sw = (float4*)(smem + SM_SW);

    for (int e = tid; e < 1152; e += 256) {
        int n = e >> 7, h = e & 127;
        int hw = hw0 + h;
        int r = hw >> 6, c = hw & 63;
        float ox = g_offb[(size_t)(b*18 + n)*HW + hw];
        float oy = g_offb[(size_t)(b*18 + 9 + n)*HW + hw];
        float px = (float)(r + 1) + (float)(n/3 - 1) + ox;
        float py = (float)(c + 1) + (float)(n%3 - 1) + oy;
        float fx = floorf(px), fy = floorf(py);
        float qx0 = fminf(fmaxf(fx,       0.f), 65.f);
        float qx1 = fminf(fmaxf(fx + 1.f, 0.f), 65.f);
        float qy0 = fminf(fmaxf(fy,       0.f), 65.f);
        float qy1 = fminf(fmaxf(fy + 1.f, 0.f), 65.f);
        float pxc = fminf(fmaxf(px, 0.f), 65.f);
        float pyc = fminf(fmaxf(py, 0.f), 65.f);
        float glt = (1.f + (qx0 - pxc)) * (1.f + (qy0 - pyc));
        float grb = (1.f - (qx1 - pxc)) * (1.f - (qy1 - pyc));
        float glb = (1.f + (qx0 - pxc)) * (1.f - (qy1 - pyc));
        float grt = (1.f - (qx1 - pxc)) * (1.f + (qy0 - pyc));
        float mod = g_mb[(size_t)(b*9 + n)*HW + hw];
        int ix0 = (int)qx0, ix1 = (int)qx1, iy0 = (int)qy0, iy1 = (int)qy1;
#define ENC(qx,qy) (((qx)>=1 && (qx)<=64 && (qy)>=1 && (qy)<=64) ? (((qx)-1)*64 + ((qy)-1)) : -1)
        si[e] = make_int4(ENC(ix0,iy0), ENC(ix1,iy1), ENC(ix0,iy1), ENC(ix1,iy0));
#undef ENC
        sw[e] = make_float4(glt*mod, grb*mod, glb*mod, grt*mod);
    }
    __syncthreads();

    int pxB  = tid & 127;
    int half = tid >> 7;
    int ocb  = (wid >> 2) * 64;
    int pxb  = (wid & 3) * 32;
    int lrow = lane & 15;
    int lkh  = (lane >> 4) * 16;

    dg_build(smem + SM_TILE, si, sw, b, 0, pxB, half, tid);
    __syncthreads();

    float acc[4][4][4];
#pragma unroll
    for (int mt = 0; mt < 4; mt++)
#pragma unroll
        for (int nt = 0; nt < 4; nt++)
#pragma unroll
            for (int q = 0; q < 4; q++) acc[mt][nt][q] = 0.f;

    for (int c = 0; c < 18; c++) {
        int p = c & 1;
        uint32_t tb = sb + SM_TILE + p*DG_BUF;
#pragma unroll
        for (int ks = 0; ks < 4; ks++) {
            int kb = ks*32 + lkh;
            uint32_t ah[4][4], al[4][4], bb[2][4];
#pragma unroll
            for (int mt = 0; mt < 4; mt++)
                ldmx4(ah[mt], tb + SW128((uint32_t)((ocb + mt*16 + lrow)*128 + kb)));
#pragma unroll
            for (int ntp = 0; ntp < 2; ntp++)
                ldmx4(bb[ntp], tb + 32768 + SW128((uint32_t)((pxb + ntp*16 + lrow)*128 + kb)));
#pragma unroll
            for (int mt = 0; mt < 4; mt++)
#pragma unroll
                for (int nt = 0; nt < 4; nt++)
                    mma_f16(acc[mt][nt], ah[mt], bb[nt>>1][nt&1], bb[nt>>1][(nt&1)+2]);
#pragma unroll
            for (int mt = 0; mt < 4; mt++)
                ldmx4(al[mt], tb + 16384 + SW128((uint32_t)((ocb + mt*16 + lrow)*128 + kb)));
#pragma unroll
            for (int mt = 0; mt < 4; mt++)
#pragma unroll
                for (int nt = 0; nt < 4; nt++)
                    mma_f16(acc[mt][nt], al[mt], bb[nt>>1][nt&1], bb[nt>>1][(nt&1)+2]);
        }
        if (c < 17)
            dg_build(smem + SM_TILE + (1-p)*DG_BUF, si, sw, b, c + 1, pxB, half, tid);
        __syncthreads();
    }

    int g  = lane >> 2;
    int cx = (lane & 3) * 2;
#pragma unroll
    for (int mt = 0; mt < 4; mt++) {
#pragma unroll
        for (int nt = 0; nt < 4; nt++) {
            int oc = ocb + mt*16 + g;
            int px = pxb + nt*8 + cx;
            float* d0 = g_d + ((size_t)(b*CH + oc))*HW + hw0 + px;
            float* d1 = g_d + ((size_t)(b*CH + oc + 8))*HW + hw0 + px;
            *(float2*)d0 = make_float2(acc[mt][nt][0], acc[mt][nt][1]);
            *(float2*)d1 = make_float2(acc[mt][nt][2], acc[mt][nt][3]);
        }
    }

    // ---- BN1 stats epilogue: per-CTA per-channel (sum, sumsq) ----
    float* sp = (float*)smem;          // [128][4]
    float* sq = sp + 512;              // [128][4]
    __syncthreads();
#pragma unroll
    for (int mt = 0; mt < 4; mt++) {
#pragma unroll
        for (int h2 = 0; h2 < 2; h2++) {
            float s = 0.f, q = 0.f;
#pragma unroll
            for (int nt = 0; nt < 4; nt++) {
                float v0 = acc[mt][nt][h2*2], v1 = acc[mt][nt][h2*2 + 1];
                s += v0 + v1;
                q += v0*v0 + v1*v1;
            }
            s += __shfl_xor_sync(0xffffffffu, s, 1);
            q += __shfl_xor_sync(0xffffffffu, q, 1);
            s += __shfl_xor_sync(0xffffffffu, s, 2);
            q += __shfl_xor_sync(0xffffffffu, q, 2);
            if ((lane & 3) == 0) {
                int oc = ocb + mt*16 + g + h2*8;
                sp[oc*4 + (wid & 3)] = s;
                sq[oc*4 + (wid & 3)] = q;
            }
        }
    }
    __syncthreads();
    if (tid < 128) {
        float S = sp[tid*4] + sp[tid*4+1] + sp[tid*4+2] + sp[tid*4+3];
        float Q = sq[tid*4] + sq[tid*4+1] + sq[tid*4+2] + sq[tid*4+3];
        g_p1s[tid*256 + blockIdx.x] = S;
        g_p1q[tid*256 + blockIdx.x] = Q;
    }
}

// ---------------- K7: fused red1 + bn1 + gelu + depthwise2 + stats2 ---------
__global__ __launch_bounds__(256) void k_bngelu_dw2(const float* __restrict__ g,
                                                    const float* __restrict__ bv,
                                                    const float* __restrict__ w,
                                                    const float* __restrict__ bias) {
    __shared__ float T[66*68];
    __shared__ float rs[256], rq[256];
    __shared__ float stat[2];
    int tid = threadIdx.x;
    int blk = blockIdx.x;          // (b, ch): 8*128
    int ch = blk & 127;

    rs[tid] = g_p1s[ch*256 + tid];
    rq[tid] = g_p1q[ch*256 + tid];
    __syncthreads();
    for (int o = 128; o > 0; o >>= 1) {
        if (tid < o) { rs[tid] += rs[tid+o]; rq[tid] += rq[tid+o]; }
        __syncthreads();
    }
    if (tid == 0) {
        float mean = rs[0] * (1.f/32768.f);
        float var  = rq[0] * (1.f/32768.f) - mean*mean;
        stat[0] = mean;
        stat[1] = rsqrtf(var + 1e-5f);
    }
    __syncthreads();
    float scale = stat[1] * g[ch];
    float shift = bv[ch] - stat[0] * scale;
    const float* src = g_d + (size_t)blk*HW;

    for (int e = tid; e < 66*66; e += 256) {
        int r = e/66, c = e - (e/66)*66;
        int rr = r - 1, cc = c - 1;
        float v = 0.f;
        if ((unsigned)rr < 64u && (unsigned)cc < 64u) {
            float xn = src[rr*64 + cc] * scale + shift;
            v = 0.5f * xn * (1.f + erff(xn * 0.70710678118654752f));
        }
        T[r*68 + c] = v;
    }
    __syncthreads();

    const float* wc = w + ch*9;
    float w0 = wc[0], w1 = wc[1], w2 = wc[2], w3 = wc[3], w4 = wc[4],
          w5 = wc[5], w6 = wc[6], w7 = wc[7], w8 = wc[8];
    float bb = bias[ch];
    float* dst = g_u + (size_t)blk*HW;
    float s = 0.f, q = 0.f;
#pragma unroll
    for (int i = 0; i < 16; i++) {
        int px = i*256 + tid;
        int r = px >> 6, c = px & 63;
        const float* t0 = T + r*68 + c;
        float v = bb
            + w0*t0[0]     + w1*t0[1]     + w2*t0[2]
            + w3*t0[68]    + w4*t0[69]    + w5*t0[70]
            + w6*t0[136]   + w7*t0[137]   + w8*t0[138];
        dst[px] = v;
        s += v;
        q += v*v;
    }
    rs[tid] = s; rq[tid] = q;
    __syncthreads();
    for (int o = 128; o > 0; o >>= 1) {
        if (tid < o) { rs[tid] += rs[tid+o]; rq[tid] += rq[tid+o]; }
        __syncthreads();
    }
    if (tid == 0) { g_p2s[blk] = rs[0]; g_p2q[blk] = rq[0]; }
}

// ---------------- K9: fused red2 + bn2 + relu -> out (float4) ----------------
__global__ __launch_bounds__(256) void k_bn2relu(const float* __restrict__ g,
                                                 const float* __restrict__ bv,
                                                 float* __restrict__ out) {
    __shared__ float stat[2];
    int i = blockIdx.x * 256 + threadIdx.x;      // float4 index
    int ch = ((blockIdx.x * 1024) >> 12) & (CH-1);
    if (threadIdx.x == 0) {
        float s = 0.f, q = 0.f;
#pragma unroll
        for (int b = 0; b < BB; b++) {
            s += g_p2s[b*CH + ch];
            q += g_p2q[b*CH + ch];
        }
        float mean = s * (1.f/32768.f);
        float var  = q * (1.f/32768.f) - mean*mean;
        stat[0] = mean;
        stat[1] = rsqrtf(var + 1e-5f);
    }
    __syncthreads();
    if (i >= BB*CH*HW/4) return;
    float scale = stat[1] * g[ch];
    float shift = bv[ch] - stat[0] * scale;
    float4 v = *(const float4*)&g_u[(size_t)i*4];
    float4 o;
    o.x = fmaxf(v.x*scale + shift, 0.f);
    o.y = fmaxf(v.y*scale + shift, 0.f);
    o.z = fmaxf(v.z*scale + shift, 0.f);
    o.w = fmaxf(v.w*scale + shift, 0.f);
    *(float4*)&out[(size_t)i*4] = o;
}

// ---------------- launch ----------------------------------------------------
extern "C" void kernel_launch(void* const* d_in, const int* in_sizes, int n_in,
                              void* d_out, int out_size) {
    const float* x1      = (const float*)d_in[0];
    const float* x2      = (const float*)d_in[1];
    const float* dw1_w   = (const float*)d_in[2];
    const float* dw1_b   = (const float*)d_in[3];
    const float* pw_w    = (const float*)d_in[4];
    const float* pw_b    = (const float*)d_in[5];
    const float* p_w     = (const float*)d_in[6];
    const float* p_b     = (const float*)d_in[7];
    const float* m_w     = (const float*)d_in[8];
    const float* m_b     = (const float*)d_in[9];
    const float* dcn_w   = (const float*)d_in[10];
    const float* bn1_g   = (const float*)d_in[11];
    const float* bn1_b   = (const float*)d_in[12];
    const float* dw2_w   = (const float*)d_in[13];
    const float* dw2_b   = (const float*)d_in[14];
    const float* bn2_g   = (const float*)d_in[15];
    const float* bn2_b   = (const float*)d_in[16];
    float* out = (float*)d_out;

    cudaFuncSetAttribute(k_dgemm_tc,   cudaFuncAttributeMaxDynamicSharedMemorySize, SMEM_DG);
    cudaFuncSetAttribute(k_pw_tc,      cudaFuncAttributeMaxDynamicSharedMemorySize, SMEM_PW);
    cudaFuncSetAttribute(k_offmask_tc, cudaFuncAttributeMaxDynamicSharedMemorySize, SMEM_OM);

    int prep_items = 18*16384 + 4*16384 + 18*4096;
    k_prep <<<(prep_items + 255)/256, 256>>>(dcn_w, pw_w, p_w, m_w);
    k_updw1<<<BB*CC, 256>>>(x1, x2, dw1_w, dw1_b);
    k_pw_tc<<<PP/128, 256, SMEM_PW>>>(pw_b);
    k_offmask_tc<<<PP/128, 256, SMEM_OM>>>(p_b, m_b);
    k_dgemm_tc<<<PP/128, 256, SMEM_DG>>>();
    k_bngelu_dw2<<<BB*CH, 256>>>(bn1_g, bn1_b, dw2_w, dw2_b);
    k_bn2relu<<<BB*CH*HW/4/256, 256>>>(bn2_g, bn2_b, out);  // 4096 blocks
}

// round 13
// speedup vs baseline: 1.5878x; 1.2317x over previous
#include <cuda_runtime.h>
#include <cuda_fp16.h>
#include <math.h>
#include <cstdint>

#define BB 8
#define CH 128
#define CC 256
#define HW 4096
#define PP 32768      // BB*HW
#define KBIG 1152     // 128 ic * 9 taps

// ---------------- scratch (static device globals; no runtime alloc) --------
static __device__ float  g_h1 [BB*CC*HW];     // fused upcat+depthwise1 out
static __device__ float  g_h  [BB*CH*HW];     // pointwise out
static __device__ float  g_offb[BB*18*HW];    // offsets
static __device__ float  g_mb [BB*9*HW];      // modulation (sigmoid)
static __device__ float  g_d  [BB*CH*HW];     // deform conv out
static __device__ float  g_u  [BB*CH*HW];     // depthwise2 out
static __device__ float  g_p1s[CH*256];       // dgemm per-CTA channel sums
static __device__ float  g_p1q[CH*256];       // dgemm per-CTA channel sumsq
static __device__ float  g_p2s[BB*CH];        // dw2 per-CTA sums
static __device__ float  g_p2q[BB*CH];        // dw2 per-CTA sumsq
static __device__ __half g_wA [18*8192];      // dcn w: fp16 SW128 images
static __device__ __half g_pwA[4*8192];       // pw w: fp16 SW128 images
static __device__ __half g_omA[18*2048];      // off+mask w: fp16 images

#define SW128(o)   ((o) ^ (((o) >> 3) & 0x70))

__device__ __forceinline__ uint32_t smem_u32(const void* p) {
    uint32_t a;
    asm("{ .reg .u64 t; cvta.to.shared.u64 t, %1; cvt.u32.u64 %0, t; }"
        : "=r"(a) : "l"(p));
    return a;
}
__device__ __forceinline__ void ldmx4(uint32_t* r, uint32_t addr) {
    asm volatile("ldmatrix.sync.aligned.m8n8.x4.shared.b16 {%0,%1,%2,%3}, [%4];"
                 : "=r"(r[0]), "=r"(r[1]), "=r"(r[2]), "=r"(r[3]) : "r"(addr));
}
__device__ __forceinline__ void mma_f16(float* d, const uint32_t* a,
                                        uint32_t b0, uint32_t b1) {
    asm volatile("mma.sync.aligned.m16n8k16.row.col.f32.f16.f16.f32 "
                 "{%0,%1,%2,%3}, {%4,%5,%6,%7}, {%8,%9}, {%0,%1,%2,%3};"
                 : "+f"(d[0]), "+f"(d[1]), "+f"(d[2]), "+f"(d[3])
                 : "r"(a[0]), "r"(a[1]), "r"(a[2]), "r"(a[3]), "r"(b0), "r"(b1));
}
__device__ __forceinline__ uint32_t pack_h2(float v0, float v1) {
    __half2 h = __floats2half2_rn(v0, v1);
    return *(uint32_t*)&h;
}
__device__ __forceinline__ void hi_store4(unsigned char* hi, uint32_t off,
                                          const float* v) {
    uint2 w;
    w.x = pack_h2(v[0], v[1]);
    w.y = pack_h2(v[2], v[3]);
    *(uint2*)(hi + off) = w;
}

// ---------------- K0: weight prep (fp16 SW128 images) -----------------------
__global__ __launch_bounds__(256) void k_prep(const float* __restrict__ dcn_w,
                                              const float* __restrict__ pw_w,
                                              const float* __restrict__ p_w,
                                              const float* __restrict__ m_w) {
    int i = blockIdx.x * 256 + threadIdx.x;
    if (i < 18*8192) {
        int c = i >> 13, e = i & 8191;
        int oc = e >> 6, ic = e & 63;
        int tap = c >> 1, ichalf = c & 1;
        float val = dcn_w[oc*KBIG + (ichalf*64 + ic)*9 + tap];
        g_wA[(size_t)c*8192 + (SW128((uint32_t)(oc*128 + ic*2)) >> 1)] = __float2half(val);
        return;
    }
    i -= 18*8192;
    if (i < 4*8192) {
        int c = i >> 13, e = i & 8191;
        int oc = e >> 6, ic = e & 63;
        float val = pw_w[oc*CC + c*64 + ic];
        g_pwA[(size_t)c*8192 + (SW128((uint32_t)(oc*128 + ic*2)) >> 1)] = __float2half(val);
        return;
    }
    i -= 4*8192;
    if (i < 18*2048) {
        int c = i >> 11, e = i & 2047;
        int oc = e >> 6, ic = e & 63;
        int tap = c >> 1, ichalf = c & 1;
        int icg = ichalf*64 + ic;
        float val = 0.f;
        if (oc < 18)      val = p_w[oc*KBIG + icg*9 + tap];
        else if (oc < 27) val = m_w[(oc-18)*KBIG + icg*9 + tap];
        g_omA[(size_t)c*2048 + (SW128((uint32_t)(oc*128 + ic*2)) >> 1)] = __float2half(val);
    }
}

// ---------------- K1: fused bilinear-up2x + concat + depthwise1 -------------
__global__ __launch_bounds__(256) void k_updw1(const float* __restrict__ x1,
                                               const float* __restrict__ x2,
                                               const float* __restrict__ w,
                                               const float* __restrict__ bias) {
    __shared__ float T[66*68];
    __shared__ float X1[32*33];
    int tid = threadIdx.x;
    int blk = blockIdx.x;
    int b = blk >> 8, ch = blk & 255;

    if (ch < CH) {
        const float* img = x2 + (size_t)(b*CH + ch)*HW;
        for (int e = tid; e < 66*66; e += 256) {
            int r = e/66, c = e - (e/66)*66;
            int rr = r - 1, cc = c - 1;
            T[r*68 + c] = ((unsigned)rr < 64u && (unsigned)cc < 64u) ? img[rr*64 + cc] : 0.f;
        }
    } else {
        const float* img = x1 + ((size_t)(b*CH + ch - CH))*1024;
        for (int e = tid; e < 1024; e += 256)
            X1[(e >> 5)*33 + (e & 31)] = img[e];
        __syncthreads();
        for (int e = tid; e < 66*66; e += 256) {
            int r = e/66, c = e - (e/66)*66;
            int rr = r - 1, cc = c - 1;
            float v = 0.f;
            if ((unsigned)rr < 64u && (unsigned)cc < 64u) {
                float sr = (float)rr * (31.0f/63.0f);
                float sc = (float)cc * (31.0f/63.0f);
                int i0 = min((int)sr, 30);
                int j0 = min((int)sc, 30);
                float ty = sr - (float)i0;
                float tx = sc - (float)j0;
                float a00 = X1[i0*33 + j0],     a10 = X1[(i0+1)*33 + j0];
                float a01 = X1[i0*33 + j0 + 1], a11 = X1[(i0+1)*33 + j0 + 1];
                v = (a00*(1.f-ty) + a10*ty)*(1.f-tx) + (a01*(1.f-ty) + a11*ty)*tx;
            }
            T[r*68 + c] = v;
        }
    }
    __syncthreads();

    const float* wc = w + ch*9;
    float w0 = wc[0], w1 = wc[1], w2 = wc[2], w3 = wc[3], w4 = wc[4],
          w5 = wc[5], w6 = wc[6], w7 = wc[7], w8 = wc[8];
    float bb = bias[ch];
    float* dst = g_h1 + (size_t)blk*HW;
#pragma unroll
    for (int i = 0; i < 16; i++) {
        int px = i*256 + tid;
        int r = px >> 6, c = px & 63;
        const float* t0 = T + r*68 + c;
        dst[px] = bb
            + w0*t0[0]     + w1*t0[1]     + w2*t0[2]
            + w3*t0[68]    + w4*t0[69]    + w5*t0[70]
            + w6*t0[136]   + w7*t0[137]   + w8*t0[138];
    }
}

// ---------------- K3: pointwise 256->128 via mma.sync fp16 ------------------
// buf: A 16K | B 16K = 32KB
#define PW_BUF  32768
#define SMEM_PW (2*PW_BUF)
__device__ __forceinline__ void pw_build(unsigned char* nb, int b, int c,
                                         int hw0, int tid) {
    float4* dstA = (float4*)nb;
    const float4* srcA = (const float4*)((const unsigned char*)g_pwA + (size_t)c*16384);
#pragma unroll
    for (int i = 0; i < 4; i++) dstA[tid + i*256] = srcA[tid + i*256];
    int pxB  = tid & 127;
    int half = tid >> 7;
    const float* img = g_h1 + ((size_t)(b*CC + c*64 + half*32))*HW + hw0 + pxB;
    unsigned char* bhi = nb + 16384;
#pragma unroll
    for (int ip = 0; ip < 8; ip++) {
        float v[4];
#pragma unroll
        for (int j = 0; j < 4; j++) { v[j] = img[0]; img += HW; }
        hi_store4(bhi, SW128((uint32_t)(pxB*128 + (half*32 + ip*4)*2)), v);
    }
}

__global__ __launch_bounds__(256, 1) void k_pw_tc(const float* __restrict__ bias) {
    extern __shared__ __align__(1024) unsigned char smem[];
    uint32_t sb = smem_u32(smem);
    int tid  = threadIdx.x;
    int lane = tid & 31;
    int wid  = tid >> 5;
    int pxg0 = blockIdx.x * 128;
    int b   = pxg0 >> 12;
    int hw0 = pxg0 & 4095;

    int ocb  = (wid >> 2) * 64;
    int pxb  = (wid & 3) * 32;
    int lrow = lane & 15;
    int lkh  = (lane >> 4) * 16;

    pw_build(smem, b, 0, hw0, tid);
    __syncthreads();

    float acc[4][4][4];
#pragma unroll
    for (int mt = 0; mt < 4; mt++)
#pragma unroll
        for (int nt = 0; nt < 4; nt++)
#pragma unroll
            for (int q = 0; q < 4; q++) acc[mt][nt][q] = 0.f;

    for (int c = 0; c < 4; c++) {
        int p = c & 1;
        uint32_t tb = sb + p*PW_BUF;
#pragma unroll
        for (int ks = 0; ks < 4; ks++) {
            int kb = ks*32 + lkh;
            uint32_t ah[4][4], bb[2][4];
#pragma unroll
            for (int mt = 0; mt < 4; mt++)
                ldmx4(ah[mt], tb + SW128((uint32_t)((ocb + mt*16 + lrow)*128 + kb)));
#pragma unroll
            for (int ntp = 0; ntp < 2; ntp++)
                ldmx4(bb[ntp], tb + 16384 + SW128((uint32_t)((pxb + ntp*16 + lrow)*128 + kb)));
#pragma unroll
            for (int mt = 0; mt < 4; mt++)
#pragma unroll
                for (int nt = 0; nt < 4; nt++)
                    mma_f16(acc[mt][nt], ah[mt], bb[nt>>1][nt&1], bb[nt>>1][(nt&1)+2]);
        }
        if (c < 3) pw_build(smem + (1-p)*PW_BUF, b, c + 1, hw0, tid);
        __syncthreads();
    }

    int g  = lane >> 2;
    int cx = (lane & 3) * 2;
#pragma unroll
    for (int mt = 0; mt < 4; mt++) {
#pragma unroll
        for (int nt = 0; nt < 4; nt++) {
            int oc = ocb + mt*16 + g;
            int px = pxb + nt*8 + cx;
            float b0 = bias[oc], b1 = bias[oc + 8];
            float* d0 = g_h + ((size_t)(b*CH + oc))*HW + hw0 + px;
            float* d1 = g_h + ((size_t)(b*CH + oc + 8))*HW + hw0 + px;
            *(float2*)d0 = make_float2(acc[mt][nt][0] + b0, acc[mt][nt][1] + b0);
            *(float2*)d1 = make_float2(acc[mt][nt][2] + b1, acc[mt][nt][3] + b1);
        }
    }
}

// ---------------- K4: offset+mask conv via mma.sync fp16 --------------------
// 18 stages of K=64; buf = A 4K | B 16K = 20KB
#define SM_NOFF  0
#define SM_OMT   5120
#define OM_BUF   20480
#define SMEM_OM  (SM_OMT + 2*OM_BUF)

__device__ __forceinline__ void om_stage(unsigned char* nb, const int* noff,
                                         int b, int c, int pxB, int half, int tid) {
    float4* dstA = (float4*)nb;
    const float4* srcA = (const float4*)((const unsigned char*)g_omA + (size_t)c*4096);
    if (tid < 256) dstA[tid] = srcA[tid];
    int tap = c >> 1, ichalf = c & 1;
    int idx = noff[tap*128 + pxB];
    const float* img = g_h + ((size_t)(b*CH + ichalf*64 + half*32))*HW;
    unsigned char* bhi = nb + 4096;
#pragma unroll
    for (int ip = 0; ip < 8; ip++) {
        float v[4];
#pragma unroll
        for (int j = 0; j < 4; j++) {
            v[j] = (idx >= 0) ? img[idx] : 0.f;
            img += HW;
        }
        hi_store4(bhi, SW128((uint32_t)(pxB*128 + (half*32 + ip*4)*2)), v);
    }
}

__global__ __launch_bounds__(256, 3) void k_offmask_tc(const float* __restrict__ pb,
                                                       const float* __restrict__ mb) {
    extern __shared__ __align__(1024) unsigned char smem[];
    uint32_t sb = smem_u32(smem);
    int* noff = (int*)(smem + SM_NOFF);
    int tid  = threadIdx.x;
    int lane = tid & 31;
    int wid  = tid >> 5;
    int pxg0 = blockIdx.x * 128;
    int b   = pxg0 >> 12;
    int hw0 = pxg0 & 4095;

    int pxB  = tid & 127;
    int half = tid >> 7;
    int pxw  = wid * 16;
    int lrow = lane & 15;
    int lkh  = (lane >> 4) * 16;

    for (int e = tid; e < 1152; e += 256) {
        int t = e >> 7, h = e & 127;
        int hw = hw0 + h;
        int r = hw >> 6, c = hw & 63;
        int dy = t/3 - 1, dx = t%3 - 1;
        int rr = r + dy, cc = c + dx;
        noff[e] = ((unsigned)rr < 64u && (unsigned)cc < 64u) ? (rr*64 + cc) : -1;
    }
    __syncthreads();

    om_stage(smem + SM_OMT, noff, b, 0, pxB, half, tid);
    __syncthreads();

    float acc[2][2][4];
#pragma unroll
    for (int mt = 0; mt < 2; mt++)
#pragma unroll
        for (int nt = 0; nt < 2; nt++)
#pragma unroll
            for (int q = 0; q < 4; q++) acc[mt][nt][q] = 0.f;

    for (int c = 0; c < 18; c++) {
        int p = c & 1;
        uint32_t tb = sb + SM_OMT + p*OM_BUF;
#pragma unroll
        for (int ks = 0; ks < 4; ks++) {
            int kb = ks*32 + lkh;
            uint32_t ah[2][4], bh[4];
#pragma unroll
            for (int mt = 0; mt < 2; mt++)
                ldmx4(ah[mt], tb + SW128((uint32_t)((mt*16 + lrow)*128 + kb)));
            ldmx4(bh, tb + 4096 + SW128((uint32_t)((pxw + lrow)*128 + kb)));
#pragma unroll
            for (int mt = 0; mt < 2; mt++)
#pragma unroll
                for (int nt = 0; nt < 2; nt++)
                    mma_f16(acc[mt][nt], ah[mt], bh[nt], bh[nt+2]);
        }
        if (c < 17)
            om_stage(smem + SM_OMT + (1-p)*OM_BUF, noff, b, c + 1, pxB, half, tid);
        __syncthreads();
    }

    int g  = lane >> 2;
    int cx = (lane & 3) * 2;
#pragma unroll
    for (int mt = 0; mt < 2; mt++) {
#pragma unroll
        for (int nt = 0; nt < 2; nt++) {
            int px = hw0 + pxw + nt*8 + cx;
#pragma unroll
            for (int h2 = 0; h2 < 2; h2++) {
                int oc = mt*16 + g + h2*8;
                float v0 = acc[mt][nt][h2*2], v1 = acc[mt][nt][h2*2 + 1];
                if (oc < 18) {
                    float bbv = pb[oc];
                    float* d = g_offb + (size_t)(b*18 + oc)*HW + px;
                    *(float2*)d = make_float2(v0 + bbv, v1 + bbv);
                } else if (oc < 27) {
                    float bbv = mb[oc - 18];
                    float* d = g_mb + (size_t)(b*9 + oc - 18)*HW + px;
                    *(float2*)d = make_float2(1.f/(1.f + expf(-(v0 + bbv))),
                                              1.f/(1.f + expf(-(v1 + bbv))));
                }
            }
        }
    }
}

// ---------------- K5: deform conv via mma.sync fp16 + stats epilogue --------
// buf: A 16K | B 16K = 32KB
#define SM_SI    0
#define SM_SW    18432
#define SM_TILE  36864
#define DG_BUF   32768
#define SMEM_DG  (SM_TILE + 2*DG_BUF)

__device__ __forceinline__ float dsample(const float* img, int4 id, float4 w) {
    float v = 0.f;
    if (id.x >= 0) v += w.x * img[id.x];
    if (id.y >= 0) v += w.y * img[id.y];
    if (id.z >= 0) v += w.z * img[id.z];
    if (id.w >= 0) v += w.w * img[id.w];
    return v;
}

__device__ __forceinline__ void dg_build(unsigned char* nb, const int4* si,
                                         const float4* sw, int b, int c,
                                         int pxB, int half, int tid) {
    float4* dstA = (float4*)nb;
    const float4* srcA = (const float4*)((const unsigned char*)g_wA + (size_t)c*16384);
#pragma unroll
    for (int i = 0; i < 4; i++) dstA[tid + i*256] = srcA[tid + i*256];
    int tap = c >> 1, ichalf = c & 1;
    int m = tap*128 + pxB;
    int4   id = si[m];
    float4 wc = sw[m];
    const float* img = g_h + ((size_t)(b*CH + ichalf*64 + half*32))*HW;
    unsigned char* bhi = nb + 16384;
#pragma unroll
    for (int ip = 0; ip < 8; ip++) {
        float v[4];
#pragma unroll
        for (int j = 0; j < 4; j++) {
            v[j] = dsample(img, id, wc);
            img += HW;
        }
        hi_store4(bhi, SW128((uint32_t)(pxB*128 + (half*32 + ip*4)*2)), v);
    }
}

__global__ __launch_bounds__(256, 1) void k_dgemm_tc() {
    extern __shared__ __align__(1024) unsigned char smem[];
    uint32_t sb = smem_u32(smem);
    int tid  = threadIdx.x;
    int lane = tid & 31;
    int wid  = tid >> 5;
    int pxg0 = blockIdx.x * 128;
    int b   = pxg0 >> 12;
    int hw0 = pxg0 & 4095;

    int4*   si = (int4*)(smem + SM_SI);
    float4* sw = (float4*)(smem + SM_SW);

    for (int e = tid; e < 1152; e += 256) {
        int n = e >> 7, h = e & 127;
        int hw = hw0 + h;
        int r = hw >> 6, c = hw & 63;
        float ox = g_offb[(size_t)(b*18 + n)*HW + hw];
        float oy = g_offb[(size_t)(b*18 + 9 + n)*HW + hw];
        float px = (float)(r + 1) + (float)(n/3 - 1) + ox;
        float py = (float)(c + 1) + (float)(n%3 - 1) + oy;
        float fx = floorf(px), fy = floorf(py);
        float qx0 = fminf(fmaxf(fx,       0.f), 65.f);
        float qx1 = fminf(fmaxf(fx + 1.f, 0.f), 65.f);
        float qy0 = fminf(fmaxf(fy,       0.f), 65.f);
        float qy1 = fminf(fmaxf(fy + 1.f, 0.f), 65.f);
        float pxc = fminf(fmaxf(px, 0.f), 65.f);
        float pyc = fminf(fmaxf(py, 0.f), 65.f);
        float glt = (1.f + (qx0 - pxc)) * (1.f + (qy0 - pyc));
        float grb = (1.f - (qx1 - pxc)) * (1.f - (qy1 - pyc));
        float glb = (1.f + (qx0 - pxc)) * (1.f - (qy1 - pyc));
        float grt = (1.f - (qx1 - pxc)) * (1.f + (qy0 - pyc));
        float mod = g_mb[(size_t)(b*9 + n)*HW + hw];
        int ix0 = (int)qx0, ix1 = (int)qx1, iy0 = (int)qy0, iy1 = (int)qy1;
#define ENC(qx,qy) (((qx)>=1 && (qx)<=64 && (qy)>=1 && (qy)<=64) ? (((qx)-1)*64 + ((qy)-1)) : -1)
        si[e] = make_int4(ENC(ix0,iy0), ENC(ix1,iy1), ENC(ix0,iy1), ENC(ix1,iy0));
#undef ENC
        sw[e] = make_float4(glt*mod, grb*mod, glb*mod, grt*mod);
    }
    __syncthreads();

    int pxB  = tid & 127;
    int half = tid >> 7;
    int ocb  = (wid >> 2) * 64;
    int pxb  = (wid & 3) * 32;
    int lrow = lane & 15;
    int lkh  = (lane >> 4) * 16;

    dg_build(smem + SM_TILE, si, sw, b, 0, pxB, half, tid);
    __syncthreads();

    float acc[4][4][4];
#pragma unroll
    for (int mt = 0; mt < 4; mt++)
#pragma unroll
        for (int nt = 0; nt < 4; nt++)
#pragma unroll
            for (int q = 0; q < 4; q++) acc[mt][nt][q] = 0.f;

    for (int c = 0; c < 18; c++) {
        int p = c & 1;
        uint32_t tb = sb + SM_TILE + p*DG_BUF;
#pragma unroll
        for (int ks = 0; ks < 4; ks++) {
            int kb = ks*32 + lkh;
            uint32_t ah[4][4], bb[2][4];
#pragma unroll
            for (int mt = 0; mt < 4; mt++)
                ldmx4(ah[mt], tb + SW128((uint32_t)((ocb + mt*16 + lrow)*128 + kb)));
#pragma unroll
            for (int ntp = 0; ntp < 2; ntp++)
                ldmx4(bb[ntp], tb + 16384 + SW128((uint32_t)((pxb + ntp*16 + lrow)*128 + kb)));
#pragma unroll
            for (int mt = 0; mt < 4; mt++)
#pragma unroll
                for (int nt = 0; nt < 4; nt++)
                    mma_f16(acc[mt][nt], ah[mt], bb[nt>>1][nt&1], bb[nt>>1][(nt&1)+2]);
        }
        if (c < 17)
            dg_build(smem + SM_TILE + (1-p)*DG_BUF, si, sw, b, c + 1, pxB, half, tid);
        __syncthreads();
    }

    int g  = lane >> 2;
    int cx = (lane & 3) * 2;
#pragma unroll
    for (int mt = 0; mt < 4; mt++) {
#pragma unroll
        for (int nt = 0; nt < 4; nt++) {
            int oc = ocb + mt*16 + g;
            int px = pxb + nt*8 + cx;
            float* d0 = g_d + ((size_t)(b*CH + oc))*HW + hw0 + px;
            float* d1 = g_d + ((size_t)(b*CH + oc + 8))*HW + hw0 + px;
            *(float2*)d0 = make_float2(acc[mt][nt][0], acc[mt][nt][1]);
            *(float2*)d1 = make_float2(acc[mt][nt][2], acc[mt][nt][3]);
        }
    }

    // ---- BN1 stats epilogue: per-CTA per-channel (sum, sumsq) ----
    float* sp = (float*)smem;          // [128][4]
    float* sq = sp + 512;              // [128][4]
    __syncthreads();
#pragma unroll
    for (int mt = 0; mt < 4; mt++) {
#pragma unroll
        for (int h2 = 0; h2 < 2; h2++) {
            float s = 0.f, q = 0.f;
#pragma unroll
            for (int nt = 0; nt < 4; nt++) {
                float v0 = acc[mt][nt][h2*2], v1 = acc[mt][nt][h2*2 + 1];
                s += v0 + v1;
                q += v0*v0 + v1*v1;
            }
            s += __shfl_xor_sync(0xffffffffu, s, 1);
            q += __shfl_xor_sync(0xffffffffu, q, 1);
            s += __shfl_xor_sync(0xffffffffu, s, 2);
            q += __shfl_xor_sync(0xffffffffu, q, 2);
            if ((lane & 3) == 0) {
                int oc = ocb + mt*16 + g + h2*8;
                sp[oc*4 + (wid & 3)] = s;
                sq[oc*4 + (wid & 3)] = q;
            }
        }
    }
    __syncthreads();
    if (tid < 128) {
        float S = sp[tid*4] + sp[tid*4+1] + sp[tid*4+2] + sp[tid*4+3];
        float Q = sq[tid*4] + sq[tid*4+1] + sq[tid*4+2] + sq[tid*4+3];
        g_p1s[tid*256 + blockIdx.x] = S;
        g_p1q[tid*256 + blockIdx.x] = Q;
    }
}

// ---------------- K7: fused red1 + bn1 + gelu + depthwise2 + stats2 ---------
__global__ __launch_bounds__(256) void k_bngelu_dw2(const float* __restrict__ g,
                                                    const float* __restrict__ bv,
                                                    const float* __restrict__ w,
                                                    const float* __restrict__ bias) {
    __shared__ float T[66*68];
    __shared__ float rs[256], rq[256];
    __shared__ float stat[2];
    int tid = threadIdx.x;
    int blk = blockIdx.x;          // (b, ch): 8*128
    int ch = blk & 127;

    rs[tid] = g_p1s[ch*256 + tid];
    rq[tid] = g_p1q[ch*256 + tid];
    __syncthreads();
    for (int o = 128; o > 0; o >>= 1) {
        if (tid < o) { rs[tid] += rs[tid+o]; rq[tid] += rq[tid+o]; }
        __syncthreads();
    }
    if (tid == 0) {
        float mean = rs[0] * (1.f/32768.f);
        float var  = rq[0] * (1.f/32768.f) - mean*mean;
        stat[0] = mean;
        stat[1] = rsqrtf(var + 1e-5f);
    }
    __syncthreads();
    float scale = stat[1] * g[ch];
    float shift = bv[ch] - stat[0] * scale;
    const float* src = g_d + (size_t)blk*HW;

    for (int e = tid; e < 66*66; e += 256) {
        int r = e/66, c = e - (e/66)*66;
        int rr = r - 1, cc = c - 1;
        float v = 0.f;
        if ((unsigned)rr < 64u && (unsigned)cc < 64u) {
            float xn = src[rr*64 + cc] * scale + shift;
            v = 0.5f * xn * (1.f + erff(xn * 0.70710678118654752f));
        }
        T[r*68 + c] = v;
    }
    __syncthreads();

    const float* wc = w + ch*9;
    float w0 = wc[0], w1 = wc[1], w2 = wc[2], w3 = wc[3], w4 = wc[4],
          w5 = wc[5], w6 = wc[6], w7 = wc[7], w8 = wc[8];
    float bb = bias[ch];
    float* dst = g_u + (size_t)blk*HW;
    float s = 0.f, q = 0.f;
#pragma unroll
    for (int i = 0; i < 16; i++) {
        int px = i*256 + tid;
        int r = px >> 6, c = px & 63;
        const float* t0 = T + r*68 + c;
        float v = bb
            + w0*t0[0]     + w1*t0[1]     + w2*t0[2]
            + w3*t0[68]    + w4*t0[69]    + w5*t0[70]
            + w6*t0[136]   + w7*t0[137]   + w8*t0[138];
        dst[px] = v;
        s += v;
        q += v*v;
    }
    rs[tid] = s; rq[tid] = q;
    __syncthreads();
    for (int o = 128; o > 0; o >>= 1) {
        if (tid < o) { rs[tid] += rs[tid+o]; rq[tid] += rq[tid+o]; }
        __syncthreads();
    }
    if (tid == 0) { g_p2s[blk] = rs[0]; g_p2q[blk] = rq[0]; }
}

// ---------------- K9: fused red2 + bn2 + relu -> out (float4) ----------------
__global__ __launch_bounds__(256) void k_bn2relu(const float* __restrict__ g,
                                                 const float* __restrict__ bv,
                                                 float* __restrict__ out) {
    __shared__ float stat[2];
    int i = blockIdx.x * 256 + threadIdx.x;      // float4 index
    int ch = ((blockIdx.x * 1024) >> 12) & (CH-1);
    if (threadIdx.x == 0) {
        float s = 0.f, q = 0.f;
#pragma unroll
        for (int b = 0; b < BB; b++) {
            s += g_p2s[b*CH + ch];
            q += g_p2q[b*CH + ch];
        }
        float mean = s * (1.f/32768.f);
        float var  = q * (1.f/32768.f) - mean*mean;
        stat[0] = mean;
        stat[1] = rsqrtf(var + 1e-5f);
    }
    __syncthreads();
    if (i >= BB*CH*HW/4) return;
    float scale = stat[1] * g[ch];
    float shift = bv[ch] - stat[0] * scale;
    float4 v = *(const float4*)&g_u[(size_t)i*4];
    float4 o;
    o.x = fmaxf(v.x*scale + shift, 0.f);
    o.y = fmaxf(v.y*scale + shift, 0.f);
    o.z = fmaxf(v.z*scale + shift, 0.f);
    o.w = fmaxf(v.w*scale + shift, 0.f);
    *(float4*)&out[(size_t)i*4] = o;
}

// ---------------- launch ----------------------------------------------------
extern "C" void kernel_launch(void* const* d_in, const int* in_sizes, int n_in,
                              void* d_out, int out_size) {
    const float* x1      = (const float*)d_in[0];
    const float* x2      = (const float*)d_in[1];
    const float* dw1_w   = (const float*)d_in[2];
    const float* dw1_b   = (const float*)d_in[3];
    const float* pw_w    = (const float*)d_in[4];
    const float* pw_b    = (const float*)d_in[5];
    const float* p_w     = (const float*)d_in[6];
    const float* p_b     = (const float*)d_in[7];
    const float* m_w     = (const float*)d_in[8];
    const float* m_b     = (const float*)d_in[9];
    const float* dcn_w   = (const float*)d_in[10];
    const float* bn1_g   = (const float*)d_in[11];
    const float* bn1_b   = (const float*)d_in[12];
    const float* dw2_w   = (const float*)d_in[13];
    const float* dw2_b   = (const float*)d_in[14];
    const float* bn2_g   = (const float*)d_in[15];
    const float* bn2_b   = (const float*)d_in[16];
    float* out = (float*)d_out;

    cudaFuncSetAttribute(k_dgemm_tc,   cudaFuncAttributeMaxDynamicSharedMemorySize, SMEM_DG);
    cudaFuncSetAttribute(k_pw_tc,      cudaFuncAttributeMaxDynamicSharedMemorySize, SMEM_PW);
    cudaFuncSetAttribute(k_offmask_tc, cudaFuncAttributeMaxDynamicSharedMemorySize, SMEM_OM);

    int prep_items = 18*8192 + 4*8192 + 18*2048;
    k_prep <<<(prep_items + 255)/256, 256>>>(dcn_w, pw_w, p_w, m_w);
    k_updw1<<<BB*CC, 256>>>(x1, x2, dw1_w, dw1_b);
    k_pw_tc<<<PP/128, 256, SMEM_PW>>>(pw_b);
    k_offmask_tc<<<PP/128, 256, SMEM_OM>>>(p_b, m_b);
    k_dgemm_tc<<<PP/128, 256, SMEM_DG>>>();
    k_bngelu_dw2<<<BB*CH, 256>>>(bn1_g, bn1_b, dw2_w, dw2_b);
    k_bn2relu<<<BB*CH*HW/4/256, 256>>>(bn2_g, bn2_b, out);  // 4096 blocks
}